// round 7
// baseline (speedup 1.0000x reference)
#include <cuda_runtime.h>
#include <cuda_bf16.h>
#include <cstdint>

// ---------------------------------------------------------------------------
// Problem: B=16, S=512, F=512, H=8, D=512.
// All GEMM operands pre-split into bf16 hi/lo planes (x = hi + lo).
// ---------------------------------------------------------------------------
__device__ float g_V[16 * 512 * 4096];      // V projection fp32 (pre-transpose)
__device__ float g_P[128 * 512 * 512];      // scores fp32 (softmax input)

__device__ __nv_bfloat16 g_xh[8192 * 512],       g_xl[8192 * 512];
__device__ __nv_bfloat16 g_WTh[3 * 4096 * 512],  g_WTl[3 * 4096 * 512];
__device__ __nv_bfloat16 g_Qh[8192 * 4096],      g_Ql[8192 * 4096];
__device__ __nv_bfloat16 g_Kh[8192 * 4096],      g_Kl[8192 * 4096];
__device__ __nv_bfloat16 g_VTh[128 * 512 * 512], g_VTl[128 * 512 * 512];
__device__ __nv_bfloat16 g_Ph[128 * 512 * 512],  g_Pl[128 * 512 * 512];

// ===========================================================================
// Helpers
// ===========================================================================
__device__ __forceinline__ uint32_t smem_u32(const void* p) {
    uint32_t a;
    asm("{ .reg .u64 t; cvta.to.shared.u64 t, %1; cvt.u32.u64 %0, t; }"
        : "=r"(a) : "l"(p));
    return a;
}

__device__ __forceinline__ void cp16(uint32_t dst, const void* src) {
    asm volatile("cp.async.cg.shared.global [%0], [%1], 16;"
                 :: "r"(dst), "l"(src) : "memory");
}
#define CP_COMMIT() asm volatile("cp.async.commit_group;" ::: "memory")
#define CP_WAIT0()  asm volatile("cp.async.wait_group 0;" ::: "memory")

// pack two fp32 into bf16x2 hi-plane word + lo-plane word (rn rounding)
__device__ __forceinline__ void pack2(float x0, float x1, uint32_t& h, uint32_t& l) {
    asm("cvt.rn.bf16x2.f32 %0, %1, %2;" : "=r"(h) : "f"(x1), "f"(x0));
    float f0 = __uint_as_float(h << 16);
    float f1 = __uint_as_float(h & 0xFFFF0000u);
    float l0 = x0 - f0, l1 = x1 - f1;
    asm("cvt.rn.bf16x2.f32 %0, %1, %2;" : "=r"(l) : "f"(l1), "f"(l0));
}

// D += A * B : m16n8k16 bf16, row.col, fp32 accumulate
__device__ __forceinline__ void mma16(float* c, const uint32_t* a, const uint32_t* b) {
    asm volatile(
        "mma.sync.aligned.m16n8k16.row.col.f32.bf16.bf16.f32 "
        "{%0,%1,%2,%3}, {%4,%5,%6,%7}, {%8,%9}, {%0,%1,%2,%3};"
        : "+f"(c[0]), "+f"(c[1]), "+f"(c[2]), "+f"(c[3])
        : "r"(a[0]), "r"(a[1]), "r"(a[2]), "r"(a[3]), "r"(b[0]), "r"(b[1]));
}

__device__ __forceinline__ void ldsm4(uint32_t* r, uint32_t addr) {
    asm volatile("ldmatrix.sync.aligned.m8n8.x4.shared.b16 {%0,%1,%2,%3}, [%4];"
                 : "=r"(r[0]), "=r"(r[1]), "=r"(r[2]), "=r"(r[3]) : "r"(addr));
}

// ===========================================================================
// NT GEMM on bf16 hi/lo planes (3-term emulation of fp32).
//   C[128x256] = A[M,512] @ B[N,512]^T   (planes row-major, K contiguous)
// 256 threads = 8 warps (2M x 4N), warp tile 64x64, m16n8k16 frags.
// SMEM stage (KB=32): each tile row = 128B: chunks 0-3 = hi k0..31,
// chunks 4-7 = lo k0..31, chunk swizzle c ^= (row&7).
//   A rows 0..127 @ [0,16384) ; B rows 0..255 @ [16384,49152)
// 2-stage double buffer (96KB total) -> 2 CTAs/SM.
// ===========================================================================
#define KB        32
#define NKB       16
#define NSTG      2
#define STAGE     49152
#define GEMM_SMEM (NSTG * STAGE)   // 98304

// EPI: 0 -> write fp32 C;  1 -> write bf16 hi/lo planes Ch/Cl
template <int EPI>
__device__ __forceinline__ void gemm_nt_bf16(
    const __nv_bfloat16* __restrict__ Ah, const __nv_bfloat16* __restrict__ Al, int lda,
    const __nv_bfloat16* __restrict__ Bh, const __nv_bfloat16* __restrict__ Bl, int ldb,
    float* __restrict__ C, __nv_bfloat16* __restrict__ Ch,
    __nv_bfloat16* __restrict__ Cl, int ldc)
{
    extern __shared__ __align__(128) char smc[];
    const uint32_t sa = smem_u32(smc);

    const int tid = threadIdx.x;
    const int wid = tid >> 5;
    const int lid = tid & 31;
    const int wr  = wid >> 2;        // 0..1 (M)
    const int wc  = wid & 3;         // 0..3 (N)
    const int g   = lid >> 2;        // 0..7
    const int tg  = lid & 3;         // 0..3

    const __nv_bfloat16* Abh = Ah + (size_t)(blockIdx.y * 128) * lda;
    const __nv_bfloat16* Abl = Al + (size_t)(blockIdx.y * 128) * lda;
    const __nv_bfloat16* Bbh = Bh + (size_t)(blockIdx.x * 256) * ldb;
    const __nv_bfloat16* Bbl = Bl + (size_t)(blockIdx.x * 256) * ldb;

    // cp.async task decomposition: t -> (row, chunk c). dest swizzled.
    auto load_stage = [&](int buf, int kb) {
        const uint32_t dbase = sa + buf * STAGE;
        const int kc = kb * KB;
#pragma unroll
        for (int i = 0; i < 4; ++i) {               // A: 1024 chunks
            const int t = tid + (i << 8);
            const int row = t >> 3, c = t & 7;
            const __nv_bfloat16* src =
                ((c & 4) ? Abl : Abh) + (size_t)row * lda + kc + (c & 3) * 8;
            cp16(dbase + row * 128 + ((c ^ (row & 7)) << 4), src);
        }
#pragma unroll
        for (int i = 0; i < 8; ++i) {               // B: 2048 chunks
            const int t = tid + (i << 8);
            const int row = t >> 3, c = t & 7;
            const __nv_bfloat16* src =
                ((c & 4) ? Bbl : Bbh) + (size_t)row * ldb + kc + (c & 3) * 8;
            cp16(dbase + 16384 + row * 128 + ((c ^ (row & 7)) << 4), src);
        }
    };

    float acc[4][8][4];
#pragma unroll
    for (int mt = 0; mt < 4; ++mt)
#pragma unroll
        for (int nt = 0; nt < 8; ++nt)
#pragma unroll
            for (int i = 0; i < 4; ++i) acc[mt][nt][i] = 0.0f;

    // ldmatrix per-thread row bases: row = tilebase + (lid&15); note
    // (row&7) == (lid&7) for all our tiles, folded as XOR of (lid&7)<<4.
    const uint32_t sx  = (uint32_t)(lid & 7) << 4;
    const uint32_t hb  = (uint32_t)(lid >> 4) << 4;   // 16B half select
    uint32_t ra[4], rb[4];
#pragma unroll
    for (int mt = 0; mt < 4; ++mt)
        ra[mt] = (uint32_t)(wr * 64 + mt * 16 + (lid & 15)) * 128;
#pragma unroll
    for (int n2 = 0; n2 < 4; ++n2)
        rb[n2] = 16384u + (uint32_t)(wc * 64 + n2 * 16 + (lid & 15)) * 128;

    load_stage(0, 0); CP_COMMIT();

#pragma unroll 1
    for (int kb = 0; kb < NKB; ++kb) {
        CP_WAIT0();            // stage kb landed (only pending group)
        __syncthreads();       // all warps done with buffer kb-1, see kb data
        if (kb + 1 < NKB) { load_stage((kb + 1) & 1, kb + 1); CP_COMMIT(); }

        const uint32_t sbase = sa + (kb & 1) * STAGE;

#pragma unroll
        for (int ks = 0; ks < 2; ++ks) {
            const uint32_t cvh = (uint32_t)(ks << 5) + hb;        // hi chunk<<4
            const uint32_t cvl = cvh + 64;                        // lo chunk<<4

            // ---- B fragments via ldmatrix.x4 (2 nt tiles per op) ----
            uint32_t bhv[8][2], blv[8][2];
#pragma unroll
            for (int n2 = 0; n2 < 4; ++n2) {
                const uint32_t base = sbase + rb[n2];
                uint32_t r[4];
                ldsm4(r, base + (cvh ^ sx));
                bhv[n2 * 2][0] = r[0]; bhv[n2 * 2][1] = r[2];
                bhv[n2 * 2 + 1][0] = r[1]; bhv[n2 * 2 + 1][1] = r[3];
                ldsm4(r, base + (cvl ^ sx));
                blv[n2 * 2][0] = r[0]; blv[n2 * 2][1] = r[2];
                blv[n2 * 2 + 1][0] = r[1]; blv[n2 * 2 + 1][1] = r[3];
            }

#pragma unroll
            for (int mt = 0; mt < 4; ++mt) {
                const uint32_t base = sbase + ra[mt];
                uint32_t ah[4], al[4];
                ldsm4(ah, base + (cvh ^ sx));
                ldsm4(al, base + (cvl ^ sx));
#pragma unroll
                for (int nt = 0; nt < 8; ++nt) mma16(acc[mt][nt], ah, bhv[nt]);
#pragma unroll
                for (int nt = 0; nt < 8; ++nt) mma16(acc[mt][nt], ah, blv[nt]);
#pragma unroll
                for (int nt = 0; nt < 8; ++nt) mma16(acc[mt][nt], al, bhv[nt]);
            }
        }
    }

    // ---- epilogue ----
    const int rbase = blockIdx.y * 128 + wr * 64 + g;
    const int cbase = blockIdx.x * 256 + wc * 64 + tg * 2;
#pragma unroll
    for (int mt = 0; mt < 4; ++mt) {
#pragma unroll
        for (int nt = 0; nt < 8; ++nt) {
            const int r = rbase + mt * 16;
            const int c = cbase + nt * 8;
            if (EPI == 0) {
                *reinterpret_cast<float2*>(&C[(size_t)r * ldc + c]) =
                    make_float2(acc[mt][nt][0], acc[mt][nt][1]);
                *reinterpret_cast<float2*>(&C[(size_t)(r + 8) * ldc + c]) =
                    make_float2(acc[mt][nt][2], acc[mt][nt][3]);
            } else {
                uint32_t h, l;
                pack2(acc[mt][nt][0], acc[mt][nt][1], h, l);
                *reinterpret_cast<uint32_t*>(Ch + (size_t)r * ldc + c) = h;
                *reinterpret_cast<uint32_t*>(Cl + (size_t)r * ldc + c) = l;
                pack2(acc[mt][nt][2], acc[mt][nt][3], h, l);
                *reinterpret_cast<uint32_t*>(Ch + (size_t)(r + 8) * ldc + c) = h;
                *reinterpret_cast<uint32_t*>(Cl + (size_t)(r + 8) * ldc + c) = l;
            }
        }
    }
}

// ===========================================================================
// GEMM wrappers
// ===========================================================================
__global__ void __launch_bounds__(256, 2)
proj_mm()
{
    const int z = blockIdx.z;                 // 0:Q 1:K 2:V
    const __nv_bfloat16* Bh = g_WTh + (size_t)z * 4096 * 512;
    const __nv_bfloat16* Bl = g_WTl + (size_t)z * 4096 * 512;
    if (z == 0) {
        gemm_nt_bf16<1>(g_xh, g_xl, 512, Bh, Bl, 512, nullptr, g_Qh, g_Ql, 4096);
    } else if (z == 1) {
        gemm_nt_bf16<1>(g_xh, g_xl, 512, Bh, Bl, 512, nullptr, g_Kh, g_Kl, 4096);
    } else {
        gemm_nt_bf16<0>(g_xh, g_xl, 512, Bh, Bl, 512, g_V, nullptr, nullptr, 4096);
    }
}

__global__ void __launch_bounds__(256, 2)
qk_mm()
{
    const int z = blockIdx.z;                 // h*16 + b
    const int h = z >> 4, b = z & 15;
    const size_t off = (size_t)b * 512 * 4096 + h * 512;
    gemm_nt_bf16<0>(g_Qh + off, g_Ql + off, 4096,
                    g_Kh + off, g_Kl + off, 4096,
                    g_P + (size_t)z * 512 * 512, nullptr, nullptr, 512);
}

__global__ void __launch_bounds__(256, 2)
pv_mm(float* __restrict__ out)
{
    const int z = blockIdx.z;
    const int h = z >> 4, b = z & 15;
    const size_t zo = (size_t)z * 512 * 512;
    gemm_nt_bf16<0>(g_Ph + zo, g_Pl + zo, 512,
                    g_VTh + zo, g_VTl + zo, 512,
                    out + (size_t)b * 512 * 4096 + h * 512, nullptr, nullptr, 4096);
}

// ===========================================================================
// Splits / transposes
// ===========================================================================
__global__ void split_x(const float* __restrict__ x)
{
    const size_t i = ((size_t)blockIdx.x * 256 + threadIdx.x) * 4;
    const float4 v = *reinterpret_cast<const float4*>(x + i);
    uint32_t h0, l0, h1, l1;
    pack2(v.x, v.y, h0, l0);
    pack2(v.z, v.w, h1, l1);
    *reinterpret_cast<uint2*>(g_xh + i) = make_uint2(h0, h1);
    *reinterpret_cast<uint2*>(g_xl + i) = make_uint2(l0, l1);
}

__global__ void wt_kernel(const float* __restrict__ wq,
                          const float* __restrict__ wk,
                          const float* __restrict__ wv)
{
    __shared__ float t[32][33];
    const int z = blockIdx.z;
    const float* W = (z == 0) ? wq : (z == 1) ? wk : wv;   // [512, 4096]
    __nv_bfloat16* WTh = g_WTh + (size_t)z * 4096 * 512;
    __nv_bfloat16* WTl = g_WTl + (size_t)z * 4096 * 512;
    const int n0 = blockIdx.x * 32, k0 = blockIdx.y * 32;
    const int tx = threadIdx.x, ty = threadIdx.y;
#pragma unroll
    for (int i = 0; i < 4; ++i)
        t[ty + i * 8][tx] = W[(size_t)(k0 + ty + i * 8) * 4096 + n0 + tx];
    __syncthreads();
#pragma unroll
    for (int i = 0; i < 4; ++i) {
        const float v = t[tx][ty + i * 8];
        const __nv_bfloat16 hbf = __float2bfloat16_rn(v);
        const float lo = v - __bfloat162float(hbf);
        const size_t idx = (size_t)(n0 + ty + i * 8) * 512 + k0 + tx;
        WTh[idx] = hbf;
        WTl[idx] = __float2bfloat16_rn(lo);
    }
}

__global__ void vt_kernel()
{
    __shared__ float t[32][33];
    const int z = blockIdx.z;                 // h*16 + b
    const int h = z >> 4, b = z & 15;
    const int j0 = blockIdx.x * 32, d0 = blockIdx.y * 32;
    const int tx = threadIdx.x, ty = threadIdx.y;
#pragma unroll
    for (int i = 0; i < 4; ++i)
        t[ty + i * 8][tx] = g_V[(size_t)(b * 512 + j0 + ty + i * 8) * 4096 + h * 512 + d0 + tx];
    __syncthreads();
    __nv_bfloat16* VTh = g_VTh + (size_t)z * 512 * 512;
    __nv_bfloat16* VTl = g_VTl + (size_t)z * 512 * 512;
#pragma unroll
    for (int i = 0; i < 4; ++i) {
        const float v = t[tx][ty + i * 8];
        const __nv_bfloat16 hbf = __float2bfloat16_rn(v);
        const float lo = v - __bfloat162float(hbf);
        const size_t idx = (size_t)(d0 + ty + i * 8) * 512 + j0 + tx;
        VTh[idx] = hbf;
        VTl[idx] = __float2bfloat16_rn(lo);
    }
}

// ===========================================================================
// Softmax over rows of g_P (512 wide), writes bf16 hi/lo planes.
// ===========================================================================
__global__ void softmax_kernel()
{
    const size_t row = blockIdx.x;
    const float* p = g_P + row * 512;
    const int t = threadIdx.x;  // 0..255

    float2 v = reinterpret_cast<const float2*>(p)[t];
    __shared__ float red[8];

    float m = fmaxf(v.x, v.y);
#pragma unroll
    for (int o = 16; o > 0; o >>= 1) m = fmaxf(m, __shfl_xor_sync(0xFFFFFFFFu, m, o));
    if ((t & 31) == 0) red[t >> 5] = m;
    __syncthreads();
    m = red[0];
#pragma unroll
    for (int i = 1; i < 8; i++) m = fmaxf(m, red[i]);
    __syncthreads();

    const float e0 = __expf(v.x - m);
    const float e1 = __expf(v.y - m);

    float s = e0 + e1;
#pragma unroll
    for (int o = 16; o > 0; o >>= 1) s += __shfl_xor_sync(0xFFFFFFFFu, s, o);
    if ((t & 31) == 0) red[t >> 5] = s;
    __syncthreads();
    s = red[0];
#pragma unroll
    for (int i = 1; i < 8; i++) s += red[i];

    const float inv = 1.0f / s;
    uint32_t h, l;
    pack2(e0 * inv, e1 * inv, h, l);
    reinterpret_cast<uint32_t*>(g_Ph + row * 512)[t] = h;
    reinterpret_cast<uint32_t*>(g_Pl + row * 512)[t] = l;
}

// ===========================================================================
// Launch
// ===========================================================================
extern "C" void kernel_launch(void* const* d_in, const int* in_sizes, int n_in,
                              void* d_out, int out_size)
{
    const float* x  = (const float*)d_in[0];
    const float* wq = (const float*)d_in[1];
    const float* wk = (const float*)d_in[2];
    const float* wv = (const float*)d_in[3];
    float* out = (float*)d_out;

    cudaFuncSetAttribute(proj_mm, cudaFuncAttributeMaxDynamicSharedMemorySize, GEMM_SMEM);
    cudaFuncSetAttribute(qk_mm,   cudaFuncAttributeMaxDynamicSharedMemorySize, GEMM_SMEM);
    cudaFuncSetAttribute(pv_mm,   cudaFuncAttributeMaxDynamicSharedMemorySize, GEMM_SMEM);

    split_x<<<4096, 256>>>(x);                              // x -> hi/lo planes
    wt_kernel<<<dim3(128, 16, 3), dim3(32, 8)>>>(wq, wk, wv);
    proj_mm<<<dim3(16, 64, 3), 256, GEMM_SMEM>>>();         // Q,K planes; V fp32
    vt_kernel<<<dim3(16, 16, 128), dim3(32, 8)>>>();        // V -> VT planes
    qk_mm<<<dim3(2, 4, 128), 256, GEMM_SMEM>>>();           // scores fp32
    softmax_kernel<<<65536, 256>>>();                       // -> P planes
    pv_mm<<<dim3(2, 4, 128), 256, GEMM_SMEM>>>(out);        // out fp32
}

// round 8
// speedup vs baseline: 2.4451x; 2.4451x over previous
#include <cuda_runtime.h>
#include <cuda_bf16.h>
#include <cstdint>

// ---------------------------------------------------------------------------
// Problem: B=16, S=512, F=512, H=8, D=512.
// All GEMM operands pre-split into bf16 hi/lo planes (x = hi + lo).
// ---------------------------------------------------------------------------
__device__ float g_V[16 * 512 * 4096];      // V projection fp32 (pre-transpose)

__device__ __nv_bfloat16 g_xh[8192 * 512],       g_xl[8192 * 512];
__device__ __nv_bfloat16 g_WTh[3 * 4096 * 512],  g_WTl[3 * 4096 * 512];
__device__ __nv_bfloat16 g_Qh[8192 * 4096],      g_Ql[8192 * 4096];
__device__ __nv_bfloat16 g_Kh[8192 * 4096],      g_Kl[8192 * 4096];
__device__ __nv_bfloat16 g_VTh[128 * 512 * 512], g_VTl[128 * 512 * 512];
__device__ __nv_bfloat16 g_Ph[128 * 512 * 512],  g_Pl[128 * 512 * 512];

// ===========================================================================
// Helpers
// ===========================================================================
__device__ __forceinline__ uint32_t smem_u32(const void* p) {
    uint32_t a;
    asm("{ .reg .u64 t; cvta.to.shared.u64 t, %1; cvt.u32.u64 %0, t; }"
        : "=r"(a) : "l"(p));
    return a;
}

__device__ __forceinline__ void cp16(uint32_t dst, const void* src) {
    asm volatile("cp.async.cg.shared.global [%0], [%1], 16;"
                 :: "r"(dst), "l"(src) : "memory");
}
#define CP_COMMIT() asm volatile("cp.async.commit_group;" ::: "memory")
#define CP_WAIT2()  asm volatile("cp.async.wait_group 2;" ::: "memory")
#define CP_WAIT1()  asm volatile("cp.async.wait_group 1;" ::: "memory")

// pack two fp32 into bf16x2 hi-plane word + lo-plane word (rn rounding)
__device__ __forceinline__ void pack2(float x0, float x1, uint32_t& h, uint32_t& l) {
    asm("cvt.rn.bf16x2.f32 %0, %1, %2;" : "=r"(h) : "f"(x1), "f"(x0));
    float f0 = __uint_as_float(h << 16);
    float f1 = __uint_as_float(h & 0xFFFF0000u);
    float l0 = x0 - f0, l1 = x1 - f1;
    asm("cvt.rn.bf16x2.f32 %0, %1, %2;" : "=r"(l) : "f"(l1), "f"(l0));
}

// D += A * B : m16n8k16 bf16, row.col, fp32 accumulate
__device__ __forceinline__ void mma16(float* c, const uint32_t* a, const uint32_t* b) {
    asm volatile(
        "mma.sync.aligned.m16n8k16.row.col.f32.bf16.bf16.f32 "
        "{%0,%1,%2,%3}, {%4,%5,%6,%7}, {%8,%9}, {%0,%1,%2,%3};"
        : "+f"(c[0]), "+f"(c[1]), "+f"(c[2]), "+f"(c[3])
        : "r"(a[0]), "r"(a[1]), "r"(a[2]), "r"(a[3]), "r"(b[0]), "r"(b[1]));
}

__device__ __forceinline__ void ldsm4(uint32_t* r, uint32_t addr) {
    asm volatile("ldmatrix.sync.aligned.m8n8.x4.shared.b16 {%0,%1,%2,%3}, [%4];"
                 : "=r"(r[0]), "=r"(r[1]), "=r"(r[2]), "=r"(r[3]) : "r"(addr));
}

// ===========================================================================
// NT GEMM on bf16 hi/lo planes (3-term emulation of fp32).  [R5 config]
//   C[128x256] = A[M,512] @ B[N,512]^T
// 256 threads = 8 warps (2M x 4N), warp tile 64x64, m16n8k16 frags.
// SMEM stage (KB=32): tile row = 128B (hi 64B | lo 64B), chunk swz c^=(row&7).
// 4-stage cp.async ring, 1 CTA/SM (RF-bound).
// ===========================================================================
#define KB        32
#define NKB       16
#define STAGE     49152
#define GEMM_SMEM (4 * STAGE)   // 196608

// EPI: 0 -> write fp32 C;  1 -> write bf16 hi/lo planes Ch/Cl
template <int EPI>
__device__ __forceinline__ void gemm_nt_bf16(
    const __nv_bfloat16* __restrict__ Ah, const __nv_bfloat16* __restrict__ Al, int lda,
    const __nv_bfloat16* __restrict__ Bh, const __nv_bfloat16* __restrict__ Bl, int ldb,
    float* __restrict__ C, __nv_bfloat16* __restrict__ Ch,
    __nv_bfloat16* __restrict__ Cl, int ldc)
{
    extern __shared__ __align__(128) char smc[];
    const uint32_t sa = smem_u32(smc);

    const int tid = threadIdx.x;
    const int wid = tid >> 5;
    const int lid = tid & 31;
    const int wr  = wid >> 2;
    const int wc  = wid & 3;
    const int g   = lid >> 2;
    const int tg  = lid & 3;

    const __nv_bfloat16* Abh = Ah + (size_t)(blockIdx.y * 128) * lda;
    const __nv_bfloat16* Abl = Al + (size_t)(blockIdx.y * 128) * lda;
    const __nv_bfloat16* Bbh = Bh + (size_t)(blockIdx.x * 256) * ldb;
    const __nv_bfloat16* Bbl = Bl + (size_t)(blockIdx.x * 256) * ldb;

    auto load_stage = [&](int buf, int kb) {
        const uint32_t dbase = sa + buf * STAGE;
        const int kc = kb * KB;
#pragma unroll
        for (int i = 0; i < 4; ++i) {
            const int t = tid + (i << 8);
            const int row = t >> 3, c = t & 7;
            const __nv_bfloat16* src =
                ((c & 4) ? Abl : Abh) + (size_t)row * lda + kc + (c & 3) * 8;
            cp16(dbase + row * 128 + ((c ^ (row & 7)) << 4), src);
        }
#pragma unroll
        for (int i = 0; i < 8; ++i) {
            const int t = tid + (i << 8);
            const int row = t >> 3, c = t & 7;
            const __nv_bfloat16* src =
                ((c & 4) ? Bbl : Bbh) + (size_t)row * ldb + kc + (c & 3) * 8;
            cp16(dbase + 16384 + row * 128 + ((c ^ (row & 7)) << 4), src);
        }
    };

    float acc[4][8][4];
#pragma unroll
    for (int mt = 0; mt < 4; ++mt)
#pragma unroll
        for (int nt = 0; nt < 8; ++nt)
#pragma unroll
            for (int i = 0; i < 4; ++i) acc[mt][nt][i] = 0.0f;

    const uint32_t sx = (uint32_t)(lid & 7) << 4;
    const uint32_t hb = (uint32_t)(lid >> 4) << 4;
    uint32_t ra[4], rb[4];
#pragma unroll
    for (int mt = 0; mt < 4; ++mt)
        ra[mt] = (uint32_t)(wr * 64 + mt * 16 + (lid & 15)) * 128;
#pragma unroll
    for (int n2 = 0; n2 < 4; ++n2)
        rb[n2] = 16384u + (uint32_t)(wc * 64 + n2 * 16 + (lid & 15)) * 128;

    load_stage(0, 0); CP_COMMIT();
    load_stage(1, 1); CP_COMMIT();
    load_stage(2, 2); CP_COMMIT();

#pragma unroll 1
    for (int kb = 0; kb < NKB; ++kb) {
        CP_WAIT2();
        __syncthreads();
        const uint32_t sbase = sa + (kb & 3) * STAGE;

#pragma unroll
        for (int ks = 0; ks < 2; ++ks) {
            const uint32_t cvh = (uint32_t)(ks << 5) + hb;
            const uint32_t cvl = cvh + 64;

            uint32_t bhv[8][2], blv[8][2];
#pragma unroll
            for (int n2 = 0; n2 < 4; ++n2) {
                const uint32_t base = sbase + rb[n2];
                uint32_t r[4];
                ldsm4(r, base + (cvh ^ sx));
                bhv[n2 * 2][0] = r[0]; bhv[n2 * 2][1] = r[2];
                bhv[n2 * 2 + 1][0] = r[1]; bhv[n2 * 2 + 1][1] = r[3];
                ldsm4(r, base + (cvl ^ sx));
                blv[n2 * 2][0] = r[0]; blv[n2 * 2][1] = r[2];
                blv[n2 * 2 + 1][0] = r[1]; blv[n2 * 2 + 1][1] = r[3];
            }

#pragma unroll
            for (int mt = 0; mt < 4; ++mt) {
                const uint32_t base = sbase + ra[mt];
                uint32_t ah[4], al[4];
                ldsm4(ah, base + (cvh ^ sx));
                ldsm4(al, base + (cvl ^ sx));
#pragma unroll
                for (int nt = 0; nt < 8; ++nt) mma16(acc[mt][nt], ah, bhv[nt]);
#pragma unroll
                for (int nt = 0; nt < 8; ++nt) mma16(acc[mt][nt], ah, blv[nt]);
#pragma unroll
                for (int nt = 0; nt < 8; ++nt) mma16(acc[mt][nt], al, bhv[nt]);
            }
        }

        if (kb + 3 < NKB) load_stage((kb + 3) & 3, kb + 3);
        CP_COMMIT();
    }

    const int rbase = blockIdx.y * 128 + wr * 64 + g;
    const int cbase = blockIdx.x * 256 + wc * 64 + tg * 2;
#pragma unroll
    for (int mt = 0; mt < 4; ++mt) {
#pragma unroll
        for (int nt = 0; nt < 8; ++nt) {
            const int r = rbase + mt * 16;
            const int c = cbase + nt * 8;
            if (EPI == 0) {
                *reinterpret_cast<float2*>(&C[(size_t)r * ldc + c]) =
                    make_float2(acc[mt][nt][0], acc[mt][nt][1]);
                *reinterpret_cast<float2*>(&C[(size_t)(r + 8) * ldc + c]) =
                    make_float2(acc[mt][nt][2], acc[mt][nt][3]);
            } else {
                uint32_t h, l;
                pack2(acc[mt][nt][0], acc[mt][nt][1], h, l);
                *reinterpret_cast<uint32_t*>(Ch + (size_t)r * ldc + c) = h;
                *reinterpret_cast<uint32_t*>(Cl + (size_t)r * ldc + c) = l;
                pack2(acc[mt][nt][2], acc[mt][nt][3], h, l);
                *reinterpret_cast<uint32_t*>(Ch + (size_t)(r + 8) * ldc + c) = h;
                *reinterpret_cast<uint32_t*>(Cl + (size_t)(r + 8) * ldc + c) = l;
            }
        }
    }
}

// ===========================================================================
// Fused QK^T + softmax kernel.
//   CTA tile: 64 (M rows of Q) x 512 (all N cols) per (z, m-block).
//   8 warps side-by-side in N (warp tile 64x64). 3-stage ring.
//   Stage: A 64 rows @ [0,8KB), B 512 rows @ [8KB,72KB), rows 128B swizzled.
//   Epilogue: row softmax (quad shuffle + cross-warp smem), write P planes.
// ===========================================================================
#define QK_STAGE 73728
#define QK_SMEM  (3 * QK_STAGE)   // 221184

__global__ void __launch_bounds__(256, 1)
qk_softmax()
{
    extern __shared__ __align__(128) char smc[];
    __shared__ float sm_red[64][8];
    const uint32_t sa = smem_u32(smc);

    const int z = blockIdx.z;                 // h*16 + b
    const int h = z >> 4, b = z & 15;
    const int m0 = blockIdx.x * 64;
    const size_t qoff = (size_t)(b * 512 + m0) * 4096 + h * 512;
    const size_t koff = (size_t)b * 512 * 4096 + h * 512;

    const __nv_bfloat16* Abh = g_Qh + qoff;
    const __nv_bfloat16* Abl = g_Ql + qoff;
    const __nv_bfloat16* Bbh = g_Kh + koff;
    const __nv_bfloat16* Bbl = g_Kl + koff;

    const int tid = threadIdx.x;
    const int wid = tid >> 5;
    const int lid = tid & 31;
    const int g   = lid >> 2;
    const int tg  = lid & 3;

    auto load_stage = [&](int buf, int kb) {
        const uint32_t dbase = sa + buf * QK_STAGE;
        const int kc = kb * KB;
#pragma unroll
        for (int i = 0; i < 2; ++i) {               // A: 512 chunks
            const int t = tid + (i << 8);
            const int row = t >> 3, c = t & 7;
            const __nv_bfloat16* src =
                ((c & 4) ? Abl : Abh) + (size_t)row * 4096 + kc + (c & 3) * 8;
            cp16(dbase + row * 128 + ((c ^ (row & 7)) << 4), src);
        }
#pragma unroll
        for (int i = 0; i < 16; ++i) {              // B: 4096 chunks
            const int t = tid + (i << 8);
            const int row = t >> 3, c = t & 7;
            const __nv_bfloat16* src =
                ((c & 4) ? Bbl : Bbh) + (size_t)row * 4096 + kc + (c & 3) * 8;
            cp16(dbase + 8192 + row * 128 + ((c ^ (row & 7)) << 4), src);
        }
    };

    float acc[4][8][4];
#pragma unroll
    for (int mt = 0; mt < 4; ++mt)
#pragma unroll
        for (int nt = 0; nt < 8; ++nt)
#pragma unroll
            for (int i = 0; i < 4; ++i) acc[mt][nt][i] = 0.0f;

    const uint32_t sx = (uint32_t)(lid & 7) << 4;
    const uint32_t hb = (uint32_t)(lid >> 4) << 4;
    uint32_t ra[4], rb[4];
#pragma unroll
    for (int mt = 0; mt < 4; ++mt)
        ra[mt] = (uint32_t)(mt * 16 + (lid & 15)) * 128;
#pragma unroll
    for (int n2 = 0; n2 < 4; ++n2)
        rb[n2] = 8192u + (uint32_t)(wid * 64 + n2 * 16 + (lid & 15)) * 128;

    load_stage(0, 0); CP_COMMIT();
    load_stage(1, 1); CP_COMMIT();

#pragma unroll 1
    for (int kb = 0; kb < NKB; ++kb) {
        CP_WAIT1();
        __syncthreads();
        if (kb + 2 < NKB) { load_stage((kb + 2) % 3, kb + 2); CP_COMMIT(); }
        const uint32_t sbase = sa + (kb % 3) * QK_STAGE;

#pragma unroll
        for (int ks = 0; ks < 2; ++ks) {
            const uint32_t cvh = (uint32_t)(ks << 5) + hb;
            const uint32_t cvl = cvh + 64;

            uint32_t bhv[8][2], blv[8][2];
#pragma unroll
            for (int n2 = 0; n2 < 4; ++n2) {
                const uint32_t base = sbase + rb[n2];
                uint32_t r[4];
                ldsm4(r, base + (cvh ^ sx));
                bhv[n2 * 2][0] = r[0]; bhv[n2 * 2][1] = r[2];
                bhv[n2 * 2 + 1][0] = r[1]; bhv[n2 * 2 + 1][1] = r[3];
                ldsm4(r, base + (cvl ^ sx));
                blv[n2 * 2][0] = r[0]; blv[n2 * 2][1] = r[2];
                blv[n2 * 2 + 1][0] = r[1]; blv[n2 * 2 + 1][1] = r[3];
            }

#pragma unroll
            for (int mt = 0; mt < 4; ++mt) {
                const uint32_t base = sbase + ra[mt];
                uint32_t ah[4], al[4];
                ldsm4(ah, base + (cvh ^ sx));
                ldsm4(al, base + (cvl ^ sx));
#pragma unroll
                for (int nt = 0; nt < 8; ++nt) mma16(acc[mt][nt], ah, bhv[nt]);
#pragma unroll
                for (int nt = 0; nt < 8; ++nt) mma16(acc[mt][nt], ah, blv[nt]);
#pragma unroll
                for (int nt = 0; nt < 8; ++nt) mma16(acc[mt][nt], al, bhv[nt]);
            }
        }
    }

    // ------------------- fused softmax epilogue --------------------------
    // thread holds rows rl = mt*16 + half*8 + g  (8 per thread), 16 vals each
    float rmx[4][2];
#pragma unroll
    for (int mt = 0; mt < 4; ++mt) {
#pragma unroll
        for (int hf = 0; hf < 2; ++hf) {
            float m = -1e30f;
#pragma unroll
            for (int nt = 0; nt < 8; ++nt)
                m = fmaxf(m, fmaxf(acc[mt][nt][hf * 2], acc[mt][nt][hf * 2 + 1]));
            m = fmaxf(m, __shfl_xor_sync(0xFFFFFFFFu, m, 1));
            m = fmaxf(m, __shfl_xor_sync(0xFFFFFFFFu, m, 2));
            sm_red[mt * 16 + hf * 8 + g][wid] = m;
            rmx[mt][hf] = 0.0f;
        }
    }
    __syncthreads();
#pragma unroll
    for (int mt = 0; mt < 4; ++mt)
#pragma unroll
        for (int hf = 0; hf < 2; ++hf) {
            const int rl = mt * 16 + hf * 8 + g;
            float m = sm_red[rl][0];
#pragma unroll
            for (int w = 1; w < 8; ++w) m = fmaxf(m, sm_red[rl][w]);
            rmx[mt][hf] = m;
        }
    __syncthreads();

    // exp in place + partial sums
#pragma unroll
    for (int mt = 0; mt < 4; ++mt) {
#pragma unroll
        for (int hf = 0; hf < 2; ++hf) {
            const float m = rmx[mt][hf];
            float s = 0.0f;
#pragma unroll
            for (int nt = 0; nt < 8; ++nt) {
                float e0 = __expf(acc[mt][nt][hf * 2] - m);
                float e1 = __expf(acc[mt][nt][hf * 2 + 1] - m);
                acc[mt][nt][hf * 2] = e0;
                acc[mt][nt][hf * 2 + 1] = e1;
                s += e0 + e1;
            }
            s += __shfl_xor_sync(0xFFFFFFFFu, s, 1);
            s += __shfl_xor_sync(0xFFFFFFFFu, s, 2);
            sm_red[mt * 16 + hf * 8 + g][wid] = s;
        }
    }
    __syncthreads();

    __nv_bfloat16* Ph = g_Ph + (size_t)z * 262144;
    __nv_bfloat16* Pl = g_Pl + (size_t)z * 262144;
    const int cb = wid * 64 + tg * 2;
#pragma unroll
    for (int mt = 0; mt < 4; ++mt) {
#pragma unroll
        for (int hf = 0; hf < 2; ++hf) {
            const int rl = mt * 16 + hf * 8 + g;
            float s = sm_red[rl][0];
#pragma unroll
            for (int w = 1; w < 8; ++w) s += sm_red[rl][w];
            const float inv = 1.0f / s;
            const size_t rowoff = (size_t)(m0 + rl) * 512;
#pragma unroll
            for (int nt = 0; nt < 8; ++nt) {
                uint32_t hw, lw;
                pack2(acc[mt][nt][hf * 2] * inv, acc[mt][nt][hf * 2 + 1] * inv, hw, lw);
                *reinterpret_cast<uint32_t*>(Ph + rowoff + cb + nt * 8) = hw;
                *reinterpret_cast<uint32_t*>(Pl + rowoff + cb + nt * 8) = lw;
            }
        }
    }
}

// ===========================================================================
// GEMM wrappers (proj / pv use the R5 core)
// ===========================================================================
__global__ void __launch_bounds__(256, 1)
proj_mm()
{
    const int z = blockIdx.z;                 // 0:Q 1:K 2:V
    const __nv_bfloat16* Bh = g_WTh + (size_t)z * 4096 * 512;
    const __nv_bfloat16* Bl = g_WTl + (size_t)z * 4096 * 512;
    if (z == 0) {
        gemm_nt_bf16<1>(g_xh, g_xl, 512, Bh, Bl, 512, nullptr, g_Qh, g_Ql, 4096);
    } else if (z == 1) {
        gemm_nt_bf16<1>(g_xh, g_xl, 512, Bh, Bl, 512, nullptr, g_Kh, g_Kl, 4096);
    } else {
        gemm_nt_bf16<0>(g_xh, g_xl, 512, Bh, Bl, 512, g_V, nullptr, nullptr, 4096);
    }
}

__global__ void __launch_bounds__(256, 1)
pv_mm(float* __restrict__ out)
{
    const int z = blockIdx.z;
    const int h = z >> 4, b = z & 15;
    const size_t zo = (size_t)z * 512 * 512;
    gemm_nt_bf16<0>(g_Ph + zo, g_Pl + zo, 512,
                    g_VTh + zo, g_VTl + zo, 512,
                    out + (size_t)b * 512 * 4096 + h * 512, nullptr, nullptr, 4096);
}

// ===========================================================================
// Splits / transposes
// ===========================================================================
__global__ void split_x(const float* __restrict__ x)
{
    const size_t i = ((size_t)blockIdx.x * 256 + threadIdx.x) * 4;
    const float4 v = *reinterpret_cast<const float4*>(x + i);
    uint32_t h0, l0, h1, l1;
    pack2(v.x, v.y, h0, l0);
    pack2(v.z, v.w, h1, l1);
    *reinterpret_cast<uint2*>(g_xh + i) = make_uint2(h0, h1);
    *reinterpret_cast<uint2*>(g_xl + i) = make_uint2(l0, l1);
}

__global__ void wt_kernel(const float* __restrict__ wq,
                          const float* __restrict__ wk,
                          const float* __restrict__ wv)
{
    __shared__ float t[32][33];
    const int z = blockIdx.z;
    const float* W = (z == 0) ? wq : (z == 1) ? wk : wv;   // [512, 4096]
    __nv_bfloat16* WTh = g_WTh + (size_t)z * 4096 * 512;
    __nv_bfloat16* WTl = g_WTl + (size_t)z * 4096 * 512;
    const int n0 = blockIdx.x * 32, k0 = blockIdx.y * 32;
    const int tx = threadIdx.x, ty = threadIdx.y;
#pragma unroll
    for (int i = 0; i < 4; ++i)
        t[ty + i * 8][tx] = W[(size_t)(k0 + ty + i * 8) * 4096 + n0 + tx];
    __syncthreads();
#pragma unroll
    for (int i = 0; i < 4; ++i) {
        const float v = t[tx][ty + i * 8];
        const __nv_bfloat16 hbf = __float2bfloat16_rn(v);
        const float lo = v - __bfloat162float(hbf);
        const size_t idx = (size_t)(n0 + ty + i * 8) * 512 + k0 + tx;
        WTh[idx] = hbf;
        WTl[idx] = __float2bfloat16_rn(lo);
    }
}

__global__ void vt_kernel()
{
    __shared__ float t[32][33];
    const int z = blockIdx.z;                 // h*16 + b
    const int h = z >> 4, b = z & 15;
    const int j0 = blockIdx.x * 32, d0 = blockIdx.y * 32;
    const int tx = threadIdx.x, ty = threadIdx.y;
#pragma unroll
    for (int i = 0; i < 4; ++i)
        t[ty + i * 8][tx] = g_V[(size_t)(b * 512 + j0 + ty + i * 8) * 4096 + h * 512 + d0 + tx];
    __syncthreads();
    __nv_bfloat16* VTh = g_VTh + (size_t)z * 512 * 512;
    __nv_bfloat16* VTl = g_VTl + (size_t)z * 512 * 512;
#pragma unroll
    for (int i = 0; i < 4; ++i) {
        const float v = t[tx][ty + i * 8];
        const __nv_bfloat16 hbf = __float2bfloat16_rn(v);
        const float lo = v - __bfloat162float(hbf);
        const size_t idx = (size_t)(d0 + ty + i * 8) * 512 + j0 + tx;
        VTh[idx] = hbf;
        VTl[idx] = __float2bfloat16_rn(lo);
    }
}

// ===========================================================================
// Launch
// ===========================================================================
extern "C" void kernel_launch(void* const* d_in, const int* in_sizes, int n_in,
                              void* d_out, int out_size)
{
    const float* x  = (const float*)d_in[0];
    const float* wq = (const float*)d_in[1];
    const float* wk = (const float*)d_in[2];
    const float* wv = (const float*)d_in[3];
    float* out = (float*)d_out;

    cudaFuncSetAttribute(proj_mm,    cudaFuncAttributeMaxDynamicSharedMemorySize, GEMM_SMEM);
    cudaFuncSetAttribute(qk_softmax, cudaFuncAttributeMaxDynamicSharedMemorySize, QK_SMEM);
    cudaFuncSetAttribute(pv_mm,      cudaFuncAttributeMaxDynamicSharedMemorySize, GEMM_SMEM);

    split_x<<<4096, 256>>>(x);                               // 1
    wt_kernel<<<dim3(128, 16, 3), dim3(32, 8)>>>(wq, wk, wv); // 2
    proj_mm<<<dim3(16, 64, 3), 256, GEMM_SMEM>>>();          // 3
    qk_softmax<<<dim3(8, 1, 128), 256, QK_SMEM>>>();         // 4  <- profiled slot
    vt_kernel<<<dim3(16, 16, 128), dim3(32, 8)>>>();         // 5
    pv_mm<<<dim3(2, 4, 128), 256, GEMM_SMEM>>>(out);         // 6
}

// round 9
// speedup vs baseline: 2.4803x; 1.0144x over previous
#include <cuda_runtime.h>
#include <cuda_bf16.h>
#include <cstdint>

// ---------------------------------------------------------------------------
// Problem: B=16, S=512, F=512, H=8, D=512.
// All GEMM operands pre-split into bf16 hi/lo planes (x = hi + lo).
// ---------------------------------------------------------------------------
__device__ float g_V[16 * 512 * 4096];      // V projection fp32 (pre-transpose)

__device__ __nv_bfloat16 g_xh[8192 * 512],       g_xl[8192 * 512];
__device__ __nv_bfloat16 g_WTh[3 * 4096 * 512],  g_WTl[3 * 4096 * 512];
__device__ __nv_bfloat16 g_Qh[8192 * 4096],      g_Ql[8192 * 4096];
__device__ __nv_bfloat16 g_Kh[8192 * 4096],      g_Kl[8192 * 4096];
__device__ __nv_bfloat16 g_VTh[128 * 512 * 512], g_VTl[128 * 512 * 512];
__device__ __nv_bfloat16 g_Ph[128 * 512 * 512],  g_Pl[128 * 512 * 512];

// ===========================================================================
// Helpers
// ===========================================================================
__device__ __forceinline__ uint32_t smem_u32(const void* p) {
    uint32_t a;
    asm("{ .reg .u64 t; cvta.to.shared.u64 t, %1; cvt.u32.u64 %0, t; }"
        : "=r"(a) : "l"(p));
    return a;
}

__device__ __forceinline__ void cp16(uint32_t dst, const void* src) {
    asm volatile("cp.async.cg.shared.global [%0], [%1], 16;"
                 :: "r"(dst), "l"(src) : "memory");
}
#define CP_COMMIT() asm volatile("cp.async.commit_group;" ::: "memory")
#define CP_WAIT2()  asm volatile("cp.async.wait_group 2;" ::: "memory")
#define CP_WAIT1()  asm volatile("cp.async.wait_group 1;" ::: "memory")

// pack two fp32 into bf16x2 hi-plane word + lo-plane word (rn rounding)
__device__ __forceinline__ void pack2(float x0, float x1, uint32_t& h, uint32_t& l) {
    asm("cvt.rn.bf16x2.f32 %0, %1, %2;" : "=r"(h) : "f"(x1), "f"(x0));
    float f0 = __uint_as_float(h << 16);
    float f1 = __uint_as_float(h & 0xFFFF0000u);
    float l0 = x0 - f0, l1 = x1 - f1;
    asm("cvt.rn.bf16x2.f32 %0, %1, %2;" : "=r"(l) : "f"(l1), "f"(l0));
}

// D += A * B : m16n8k16 bf16, row.col, fp32 accumulate
__device__ __forceinline__ void mma16(float* c, const uint32_t* a, const uint32_t* b) {
    asm volatile(
        "mma.sync.aligned.m16n8k16.row.col.f32.bf16.bf16.f32 "
        "{%0,%1,%2,%3}, {%4,%5,%6,%7}, {%8,%9}, {%0,%1,%2,%3};"
        : "+f"(c[0]), "+f"(c[1]), "+f"(c[2]), "+f"(c[3])
        : "r"(a[0]), "r"(a[1]), "r"(a[2]), "r"(a[3]), "r"(b[0]), "r"(b[1]));
}

__device__ __forceinline__ void ldsm4(uint32_t* r, uint32_t addr) {
    asm volatile("ldmatrix.sync.aligned.m8n8.x4.shared.b16 {%0,%1,%2,%3}, [%4];"
                 : "=r"(r[0]), "=r"(r[1]), "=r"(r[2]), "=r"(r[3]) : "r"(addr));
}

// ===========================================================================
// NT GEMM on bf16 hi/lo planes (3-term emulation of fp32), 512 threads.
//   C[128x256] = A[M,512] @ B[N,512]^T
// 16 warps: grid 2(M) x 8(N), warp tile 64x32. acc = 64 regs/thread.
// SMEM stage (KB=32): tile row = 128B (hi 64B | lo 64B), chunk swz c^=(row&7).
//   A rows 0..127 @ [0,16KB) ; B rows 0..255 @ [16KB,48KB). 4-stage ring.
// Inner loop holds one B fragment set at a time (hi.hi, lo.hi, then reload
// B-lo over it for hi.lo) to stay under 128 regs/thread.
// ===========================================================================
#define KB        32
#define NKB       16
#define STAGE     49152
#define GEMM_SMEM (4 * STAGE)   // 196608

// EPI: 0 -> write fp32 C;  1 -> write bf16 hi/lo planes Ch/Cl
template <int EPI>
__device__ __forceinline__ void gemm_nt_bf16(
    const __nv_bfloat16* __restrict__ Ah, const __nv_bfloat16* __restrict__ Al, int lda,
    const __nv_bfloat16* __restrict__ Bh, const __nv_bfloat16* __restrict__ Bl, int ldb,
    float* __restrict__ C, __nv_bfloat16* __restrict__ Ch,
    __nv_bfloat16* __restrict__ Cl, int ldc)
{
    extern __shared__ __align__(128) char smc[];
    const uint32_t sa = smem_u32(smc);

    const int tid = threadIdx.x;
    const int wid = tid >> 5;          // 0..15
    const int lid = tid & 31;
    const int wr  = wid >> 3;          // 0..1  (M)
    const int wc  = wid & 7;           // 0..7  (N)
    const int g   = lid >> 2;
    const int tg  = lid & 3;

    const __nv_bfloat16* Abh = Ah + (size_t)(blockIdx.y * 128) * lda;
    const __nv_bfloat16* Abl = Al + (size_t)(blockIdx.y * 128) * lda;
    const __nv_bfloat16* Bbh = Bh + (size_t)(blockIdx.x * 256) * ldb;
    const __nv_bfloat16* Bbl = Bl + (size_t)(blockIdx.x * 256) * ldb;

    auto load_stage = [&](int buf, int kb) {
        const uint32_t dbase = sa + buf * STAGE;
        const int kc = kb * KB;
#pragma unroll
        for (int i = 0; i < 2; ++i) {               // A: 1024 chunks
            const int t = tid + (i << 9);
            const int row = t >> 3, c = t & 7;
            const __nv_bfloat16* src =
                ((c & 4) ? Abl : Abh) + (size_t)row * lda + kc + (c & 3) * 8;
            cp16(dbase + row * 128 + ((c ^ (row & 7)) << 4), src);
        }
#pragma unroll
        for (int i = 0; i < 4; ++i) {               // B: 2048 chunks
            const int t = tid + (i << 9);
            const int row = t >> 3, c = t & 7;
            const __nv_bfloat16* src =
                ((c & 4) ? Bbl : Bbh) + (size_t)row * ldb + kc + (c & 3) * 8;
            cp16(dbase + 16384 + row * 128 + ((c ^ (row & 7)) << 4), src);
        }
    };

    float acc[4][4][4];
#pragma unroll
    for (int mt = 0; mt < 4; ++mt)
#pragma unroll
        for (int nt = 0; nt < 4; ++nt)
#pragma unroll
            for (int i = 0; i < 4; ++i) acc[mt][nt][i] = 0.0f;

    const uint32_t sx = (uint32_t)(lid & 7) << 4;
    const uint32_t hb = (uint32_t)(lid >> 4) << 4;
    uint32_t ra[4], rb[2];
#pragma unroll
    for (int mt = 0; mt < 4; ++mt)
        ra[mt] = (uint32_t)(wr * 64 + mt * 16 + (lid & 15)) * 128;
#pragma unroll
    for (int n2 = 0; n2 < 2; ++n2)
        rb[n2] = 16384u + (uint32_t)(wc * 32 + n2 * 16 + (lid & 15)) * 128;

    load_stage(0, 0); CP_COMMIT();
    load_stage(1, 1); CP_COMMIT();
    load_stage(2, 2); CP_COMMIT();

#pragma unroll 1
    for (int kb = 0; kb < NKB; ++kb) {
        CP_WAIT2();
        __syncthreads();
        const uint32_t sbase = sa + (kb & 3) * STAGE;

#pragma unroll
        for (int ks = 0; ks < 2; ++ks) {
            const uint32_t cvh = (uint32_t)(ks << 5) + hb;
            const uint32_t cvl = cvh + 64;

            uint32_t ah[4][4], al[4][4], bb[4][2];
#pragma unroll
            for (int mt = 0; mt < 4; ++mt) {
                ldsm4(ah[mt], sbase + ra[mt] + (cvh ^ sx));
                ldsm4(al[mt], sbase + ra[mt] + (cvl ^ sx));
            }
            // ---- B hi ----
#pragma unroll
            for (int n2 = 0; n2 < 2; ++n2) {
                uint32_t r[4];
                ldsm4(r, sbase + rb[n2] + (cvh ^ sx));
                bb[n2 * 2][0] = r[0]; bb[n2 * 2][1] = r[2];
                bb[n2 * 2 + 1][0] = r[1]; bb[n2 * 2 + 1][1] = r[3];
            }
#pragma unroll
            for (int mt = 0; mt < 4; ++mt)
#pragma unroll
                for (int nt = 0; nt < 4; ++nt) mma16(acc[mt][nt], ah[mt], bb[nt]);
#pragma unroll
            for (int mt = 0; mt < 4; ++mt)
#pragma unroll
                for (int nt = 0; nt < 4; ++nt) mma16(acc[mt][nt], al[mt], bb[nt]);
            // ---- B lo (reuse regs) ----
#pragma unroll
            for (int n2 = 0; n2 < 2; ++n2) {
                uint32_t r[4];
                ldsm4(r, sbase + rb[n2] + (cvl ^ sx));
                bb[n2 * 2][0] = r[0]; bb[n2 * 2][1] = r[2];
                bb[n2 * 2 + 1][0] = r[1]; bb[n2 * 2 + 1][1] = r[3];
            }
#pragma unroll
            for (int mt = 0; mt < 4; ++mt)
#pragma unroll
                for (int nt = 0; nt < 4; ++nt) mma16(acc[mt][nt], ah[mt], bb[nt]);
        }

        if (kb + 3 < NKB) load_stage((kb + 3) & 3, kb + 3);
        CP_COMMIT();
    }

    const int rbase = blockIdx.y * 128 + wr * 64 + g;
    const int cbase = blockIdx.x * 256 + wc * 32 + tg * 2;
#pragma unroll
    for (int mt = 0; mt < 4; ++mt) {
#pragma unroll
        for (int nt = 0; nt < 4; ++nt) {
            const int r = rbase + mt * 16;
            const int c = cbase + nt * 8;
            if (EPI == 0) {
                *reinterpret_cast<float2*>(&C[(size_t)r * ldc + c]) =
                    make_float2(acc[mt][nt][0], acc[mt][nt][1]);
                *reinterpret_cast<float2*>(&C[(size_t)(r + 8) * ldc + c]) =
                    make_float2(acc[mt][nt][2], acc[mt][nt][3]);
            } else {
                uint32_t h, l;
                pack2(acc[mt][nt][0], acc[mt][nt][1], h, l);
                *reinterpret_cast<uint32_t*>(Ch + (size_t)r * ldc + c) = h;
                *reinterpret_cast<uint32_t*>(Cl + (size_t)r * ldc + c) = l;
                pack2(acc[mt][nt][2], acc[mt][nt][3], h, l);
                *reinterpret_cast<uint32_t*>(Ch + (size_t)(r + 8) * ldc + c) = h;
                *reinterpret_cast<uint32_t*>(Cl + (size_t)(r + 8) * ldc + c) = l;
            }
        }
    }
}

// ===========================================================================
// Fused QK^T + softmax, 512 threads.
//   CTA tile: 64 (M) x 512 (N, full row). 16 warps: 2(M) x 8(N), warp 32x64.
//   Stage: A 64 rows @ [0,8KB), B 512 rows @ [8KB,72KB). 3-stage ring.
// ===========================================================================
#define QK_STAGE 73728
#define QK_SMEM  (3 * QK_STAGE)   // 221184

__global__ void __launch_bounds__(512, 1)
qk_softmax()
{
    extern __shared__ __align__(128) char smc[];
    __shared__ float sm_red[64][8];
    const uint32_t sa = smem_u32(smc);

    const int z = blockIdx.z;                 // h*16 + b
    const int h = z >> 4, b = z & 15;
    const int m0 = blockIdx.x * 64;
    const size_t qoff = (size_t)(b * 512 + m0) * 4096 + h * 512;
    const size_t koff = (size_t)b * 512 * 4096 + h * 512;

    const __nv_bfloat16* Abh = g_Qh + qoff;
    const __nv_bfloat16* Abl = g_Ql + qoff;
    const __nv_bfloat16* Bbh = g_Kh + koff;
    const __nv_bfloat16* Bbl = g_Kl + koff;

    const int tid = threadIdx.x;
    const int wid = tid >> 5;          // 0..15
    const int lid = tid & 31;
    const int wr  = wid >> 3;          // 0..1 (M)
    const int wc  = wid & 7;           // 0..7 (N)
    const int g   = lid >> 2;
    const int tg  = lid & 3;

    auto load_stage = [&](int buf, int kb) {
        const uint32_t dbase = sa + buf * QK_STAGE;
        const int kc = kb * KB;
        {                                            // A: 512 chunks
            const int t = tid;
            const int row = t >> 3, c = t & 7;
            const __nv_bfloat16* src =
                ((c & 4) ? Abl : Abh) + (size_t)row * 4096 + kc + (c & 3) * 8;
            cp16(dbase + row * 128 + ((c ^ (row & 7)) << 4), src);
        }
#pragma unroll
        for (int i = 0; i < 8; ++i) {                // B: 4096 chunks
            const int t = tid + (i << 9);
            const int row = t >> 3, c = t & 7;
            const __nv_bfloat16* src =
                ((c & 4) ? Bbl : Bbh) + (size_t)row * 4096 + kc + (c & 3) * 8;
            cp16(dbase + 8192 + row * 128 + ((c ^ (row & 7)) << 4), src);
        }
    };

    float acc[2][8][4];
#pragma unroll
    for (int mt = 0; mt < 2; ++mt)
#pragma unroll
        for (int nt = 0; nt < 8; ++nt)
#pragma unroll
            for (int i = 0; i < 4; ++i) acc[mt][nt][i] = 0.0f;

    const uint32_t sx = (uint32_t)(lid & 7) << 4;
    const uint32_t hb = (uint32_t)(lid >> 4) << 4;
    uint32_t ra[2], rb[4];
#pragma unroll
    for (int mt = 0; mt < 2; ++mt)
        ra[mt] = (uint32_t)(wr * 32 + mt * 16 + (lid & 15)) * 128;
#pragma unroll
    for (int n2 = 0; n2 < 4; ++n2)
        rb[n2] = 8192u + (uint32_t)(wc * 64 + n2 * 16 + (lid & 15)) * 128;

    load_stage(0, 0); CP_COMMIT();
    load_stage(1, 1); CP_COMMIT();

#pragma unroll 1
    for (int kb = 0; kb < NKB; ++kb) {
        CP_WAIT1();
        __syncthreads();
        if (kb + 2 < NKB) { load_stage((kb + 2) % 3, kb + 2); CP_COMMIT(); }
        const uint32_t sbase = sa + (kb % 3) * QK_STAGE;

#pragma unroll
        for (int ks = 0; ks < 2; ++ks) {
            const uint32_t cvh = (uint32_t)(ks << 5) + hb;
            const uint32_t cvl = cvh + 64;

            uint32_t ah[2][4], al[2][4], bb[8][2];
#pragma unroll
            for (int mt = 0; mt < 2; ++mt) {
                ldsm4(ah[mt], sbase + ra[mt] + (cvh ^ sx));
                ldsm4(al[mt], sbase + ra[mt] + (cvl ^ sx));
            }
#pragma unroll
            for (int n2 = 0; n2 < 4; ++n2) {
                uint32_t r[4];
                ldsm4(r, sbase + rb[n2] + (cvh ^ sx));
                bb[n2 * 2][0] = r[0]; bb[n2 * 2][1] = r[2];
                bb[n2 * 2 + 1][0] = r[1]; bb[n2 * 2 + 1][1] = r[3];
            }
#pragma unroll
            for (int mt = 0; mt < 2; ++mt)
#pragma unroll
                for (int nt = 0; nt < 8; ++nt) mma16(acc[mt][nt], ah[mt], bb[nt]);
#pragma unroll
            for (int mt = 0; mt < 2; ++mt)
#pragma unroll
                for (int nt = 0; nt < 8; ++nt) mma16(acc[mt][nt], al[mt], bb[nt]);
#pragma unroll
            for (int n2 = 0; n2 < 4; ++n2) {
                uint32_t r[4];
                ldsm4(r, sbase + rb[n2] + (cvl ^ sx));
                bb[n2 * 2][0] = r[0]; bb[n2 * 2][1] = r[2];
                bb[n2 * 2 + 1][0] = r[1]; bb[n2 * 2 + 1][1] = r[3];
            }
#pragma unroll
            for (int mt = 0; mt < 2; ++mt)
#pragma unroll
                for (int nt = 0; nt < 8; ++nt) mma16(acc[mt][nt], ah[mt], bb[nt]);
        }
    }

    // ------------------- fused softmax epilogue --------------------------
    // thread rows: rl = wr*32 + mt*16 + hf*8 + g  (4 per thread)
    float rmx[2][2];
#pragma unroll
    for (int mt = 0; mt < 2; ++mt) {
#pragma unroll
        for (int hf = 0; hf < 2; ++hf) {
            float m = -1e30f;
#pragma unroll
            for (int nt = 0; nt < 8; ++nt)
                m = fmaxf(m, fmaxf(acc[mt][nt][hf * 2], acc[mt][nt][hf * 2 + 1]));
            m = fmaxf(m, __shfl_xor_sync(0xFFFFFFFFu, m, 1));
            m = fmaxf(m, __shfl_xor_sync(0xFFFFFFFFu, m, 2));
            sm_red[wr * 32 + mt * 16 + hf * 8 + g][wc] = m;
        }
    }
    __syncthreads();
#pragma unroll
    for (int mt = 0; mt < 2; ++mt)
#pragma unroll
        for (int hf = 0; hf < 2; ++hf) {
            const int rl = wr * 32 + mt * 16 + hf * 8 + g;
            float m = sm_red[rl][0];
#pragma unroll
            for (int w = 1; w < 8; ++w) m = fmaxf(m, sm_red[rl][w]);
            rmx[mt][hf] = m;
        }
    __syncthreads();

#pragma unroll
    for (int mt = 0; mt < 2; ++mt) {
#pragma unroll
        for (int hf = 0; hf < 2; ++hf) {
            const float m = rmx[mt][hf];
            float s = 0.0f;
#pragma unroll
            for (int nt = 0; nt < 8; ++nt) {
                float e0 = __expf(acc[mt][nt][hf * 2] - m);
                float e1 = __expf(acc[mt][nt][hf * 2 + 1] - m);
                acc[mt][nt][hf * 2] = e0;
                acc[mt][nt][hf * 2 + 1] = e1;
                s += e0 + e1;
            }
            s += __shfl_xor_sync(0xFFFFFFFFu, s, 1);
            s += __shfl_xor_sync(0xFFFFFFFFu, s, 2);
            sm_red[wr * 32 + mt * 16 + hf * 8 + g][wc] = s;
        }
    }
    __syncthreads();

    __nv_bfloat16* Ph = g_Ph + (size_t)z * 262144;
    __nv_bfloat16* Pl = g_Pl + (size_t)z * 262144;
    const int cb = wc * 64 + tg * 2;
#pragma unroll
    for (int mt = 0; mt < 2; ++mt) {
#pragma unroll
        for (int hf = 0; hf < 2; ++hf) {
            const int rl = wr * 32 + mt * 16 + hf * 8 + g;
            float s = sm_red[rl][0];
#pragma unroll
            for (int w = 1; w < 8; ++w) s += sm_red[rl][w];
            const float inv = 1.0f / s;
            const size_t rowoff = (size_t)(m0 + rl) * 512;
#pragma unroll
            for (int nt = 0; nt < 8; ++nt) {
                uint32_t hw, lw;
                pack2(acc[mt][nt][hf * 2] * inv, acc[mt][nt][hf * 2 + 1] * inv, hw, lw);
                *reinterpret_cast<uint32_t*>(Ph + rowoff + cb + nt * 8) = hw;
                *reinterpret_cast<uint32_t*>(Pl + rowoff + cb + nt * 8) = lw;
            }
        }
    }
}

// ===========================================================================
// GEMM wrappers
// ===========================================================================
__global__ void __launch_bounds__(512, 1)
proj_mm()
{
    const int z = blockIdx.z;                 // 0:Q 1:K 2:V
    const __nv_bfloat16* Bh = g_WTh + (size_t)z * 4096 * 512;
    const __nv_bfloat16* Bl = g_WTl + (size_t)z * 4096 * 512;
    if (z == 0) {
        gemm_nt_bf16<1>(g_xh, g_xl, 512, Bh, Bl, 512, nullptr, g_Qh, g_Ql, 4096);
    } else if (z == 1) {
        gemm_nt_bf16<1>(g_xh, g_xl, 512, Bh, Bl, 512, nullptr, g_Kh, g_Kl, 4096);
    } else {
        gemm_nt_bf16<0>(g_xh, g_xl, 512, Bh, Bl, 512, g_V, nullptr, nullptr, 4096);
    }
}

__global__ void __launch_bounds__(512, 1)
pv_mm(float* __restrict__ out)
{
    const int z = blockIdx.z;
    const int h = z >> 4, b = z & 15;
    const size_t zo = (size_t)z * 512 * 512;
    gemm_nt_bf16<0>(g_Ph + zo, g_Pl + zo, 512,
                    g_VTh + zo, g_VTl + zo, 512,
                    out + (size_t)b * 512 * 4096 + h * 512, nullptr, nullptr, 4096);
}

// ===========================================================================
// Splits / transposes
// ===========================================================================
__global__ void split_x(const float* __restrict__ x)
{
    const size_t i = ((size_t)blockIdx.x * 256 + threadIdx.x) * 4;
    const float4 v = *reinterpret_cast<const float4*>(x + i);
    uint32_t h0, l0, h1, l1;
    pack2(v.x, v.y, h0, l0);
    pack2(v.z, v.w, h1, l1);
    *reinterpret_cast<uint2*>(g_xh + i) = make_uint2(h0, h1);
    *reinterpret_cast<uint2*>(g_xl + i) = make_uint2(l0, l1);
}

__global__ void wt_kernel(const float* __restrict__ wq,
                          const float* __restrict__ wk,
                          const float* __restrict__ wv, int zbase)
{
    __shared__ float t[32][33];
    const int z = zbase + blockIdx.z;
    const float* W = (z == 0) ? wq : (z == 1) ? wk : wv;   // [512, 4096]
    __nv_bfloat16* WTh = g_WTh + (size_t)z * 4096 * 512;
    __nv_bfloat16* WTl = g_WTl + (size_t)z * 4096 * 512;
    const int n0 = blockIdx.x * 32, k0 = blockIdx.y * 32;
    const int tx = threadIdx.x, ty = threadIdx.y;
#pragma unroll
    for (int i = 0; i < 4; ++i)
        t[ty + i * 8][tx] = W[(size_t)(k0 + ty + i * 8) * 4096 + n0 + tx];
    __syncthreads();
#pragma unroll
    for (int i = 0; i < 4; ++i) {
        const float v = t[tx][ty + i * 8];
        const __nv_bfloat16 hbf = __float2bfloat16_rn(v);
        const float lo = v - __bfloat162float(hbf);
        const size_t idx = (size_t)(n0 + ty + i * 8) * 512 + k0 + tx;
        WTh[idx] = hbf;
        WTl[idx] = __float2bfloat16_rn(lo);
    }
}

__global__ void vt_kernel()
{
    __shared__ float t[32][33];
    const int z = blockIdx.z;                 // h*16 + b
    const int h = z >> 4, b = z & 15;
    const int j0 = blockIdx.x * 32, d0 = blockIdx.y * 32;
    const int tx = threadIdx.x, ty = threadIdx.y;
#pragma unroll
    for (int i = 0; i < 4; ++i)
        t[ty + i * 8][tx] = g_V[(size_t)(b * 512 + j0 + ty + i * 8) * 4096 + h * 512 + d0 + tx];
    __syncthreads();
    __nv_bfloat16* VTh = g_VTh + (size_t)z * 512 * 512;
    __nv_bfloat16* VTl = g_VTl + (size_t)z * 512 * 512;
#pragma unroll
    for (int i = 0; i < 4; ++i) {
        const float v = t[tx][ty + i * 8];
        const __nv_bfloat16 hbf = __float2bfloat16_rn(v);
        const float lo = v - __bfloat162float(hbf);
        const size_t idx = (size_t)(d0 + ty + i * 8) * 512 + j0 + tx;
        VTh[idx] = hbf;
        VTl[idx] = __float2bfloat16_rn(lo);
    }
}

// ===========================================================================
// Launch
// ===========================================================================
extern "C" void kernel_launch(void* const* d_in, const int* in_sizes, int n_in,
                              void* d_out, int out_size)
{
    const float* x  = (const float*)d_in[0];
    const float* wq = (const float*)d_in[1];
    const float* wk = (const float*)d_in[2];
    const float* wv = (const float*)d_in[3];
    float* out = (float*)d_out;

    cudaFuncSetAttribute(proj_mm,    cudaFuncAttributeMaxDynamicSharedMemorySize, GEMM_SMEM);
    cudaFuncSetAttribute(qk_softmax, cudaFuncAttributeMaxDynamicSharedMemorySize, QK_SMEM);
    cudaFuncSetAttribute(pv_mm,      cudaFuncAttributeMaxDynamicSharedMemorySize, GEMM_SMEM);

    split_x<<<4096, 256>>>(x);                                   // 1
    wt_kernel<<<dim3(128, 16, 2), dim3(32, 8)>>>(wq, wk, wv, 0); // 2 (z=0,1)
    wt_kernel<<<dim3(128, 16, 1), dim3(32, 8)>>>(wq, wk, wv, 2); // 3 (z=2)
    proj_mm<<<dim3(16, 64, 3), 512, GEMM_SMEM>>>();              // 4 <- profiled
    qk_softmax<<<dim3(8, 1, 128), 512, QK_SMEM>>>();             // 5
    vt_kernel<<<dim3(16, 16, 128), dim3(32, 8)>>>();             // 6
    pv_mm<<<dim3(2, 4, 128), 512, GEMM_SMEM>>>(out);             // 7
}

// round 10
// speedup vs baseline: 2.5376x; 1.0231x over previous
#include <cuda_runtime.h>
#include <cuda_bf16.h>
#include <cstdint>

// ---------------------------------------------------------------------------
// Problem: B=16, S=512, F=512, H=8, D=512.
// All GEMM operands pre-split into bf16 hi/lo planes (x = hi + lo).
// ---------------------------------------------------------------------------
__device__ float g_V[16 * 512 * 4096];      // V projection fp32 (pre-transpose)
__device__ float g_P[128 * 512 * 512];      // scores fp32 (softmax input)

__device__ __nv_bfloat16 g_xh[8192 * 512],       g_xl[8192 * 512];
__device__ __nv_bfloat16 g_WTh[3 * 4096 * 512],  g_WTl[3 * 4096 * 512];
__device__ __nv_bfloat16 g_Qh[8192 * 4096],      g_Ql[8192 * 4096];
__device__ __nv_bfloat16 g_Kh[8192 * 4096],      g_Kl[8192 * 4096];
__device__ __nv_bfloat16 g_VTh[128 * 512 * 512], g_VTl[128 * 512 * 512];
__device__ __nv_bfloat16 g_Ph[128 * 512 * 512],  g_Pl[128 * 512 * 512];

// ===========================================================================
// Helpers
// ===========================================================================
__device__ __forceinline__ uint32_t smem_u32(const void* p) {
    uint32_t a;
    asm("{ .reg .u64 t; cvta.to.shared.u64 t, %1; cvt.u32.u64 %0, t; }"
        : "=r"(a) : "l"(p));
    return a;
}

__device__ __forceinline__ void cp16(uint32_t dst, const void* src) {
    asm volatile("cp.async.cg.shared.global [%0], [%1], 16;"
                 :: "r"(dst), "l"(src) : "memory");
}
#define CP_COMMIT() asm volatile("cp.async.commit_group;" ::: "memory")
#define CP_WAIT1()  asm volatile("cp.async.wait_group 1;" ::: "memory")

// pack two fp32 into bf16x2 hi-plane word + lo-plane word (rn rounding)
__device__ __forceinline__ void pack2(float x0, float x1, uint32_t& h, uint32_t& l) {
    asm("cvt.rn.bf16x2.f32 %0, %1, %2;" : "=r"(h) : "f"(x1), "f"(x0));
    float f0 = __uint_as_float(h << 16);
    float f1 = __uint_as_float(h & 0xFFFF0000u);
    float l0 = x0 - f0, l1 = x1 - f1;
    asm("cvt.rn.bf16x2.f32 %0, %1, %2;" : "=r"(l) : "f"(l1), "f"(l0));
}

// D += A * B : m16n8k16 bf16, row.col, fp32 accumulate
__device__ __forceinline__ void mma16(float* c, const uint32_t* a, const uint32_t* b) {
    asm volatile(
        "mma.sync.aligned.m16n8k16.row.col.f32.bf16.bf16.f32 "
        "{%0,%1,%2,%3}, {%4,%5,%6,%7}, {%8,%9}, {%0,%1,%2,%3};"
        : "+f"(c[0]), "+f"(c[1]), "+f"(c[2]), "+f"(c[3])
        : "r"(a[0]), "r"(a[1]), "r"(a[2]), "r"(a[3]), "r"(b[0]), "r"(b[1]));
}

__device__ __forceinline__ void ldsm4(uint32_t* r, uint32_t addr) {
    asm volatile("ldmatrix.sync.aligned.m8n8.x4.shared.b16 {%0,%1,%2,%3}, [%4];"
                 : "=r"(r[0]), "=r"(r[1]), "=r"(r[2]), "=r"(r[3]) : "r"(addr));
}

// ===========================================================================
// NT GEMM on bf16 hi/lo planes (3-term emulation of fp32), 256 threads.
//   C[128x64] = A[M,512] @ B[N,512]^T   (planes row-major, K contiguous)
// 8 warps: 4(M) x 2(N), warp tile 32x32. acc = 32 regs/thread.
// SMEM stage (KB=32): tile row = 128B (hi 64B | lo 64B), chunk swz c^=(row&7).
//   A rows 0..127 @ [0,16KB) ; B rows 0..63 @ [16KB,24KB). 3-stage ring.
// __launch_bounds__(256,3): 3 CTAs/SM -> 6 warps/SMSP, decorrelated barriers.
// One cp.async group committed EVERY iteration so wait_group 1 is exact.
// ===========================================================================
#define KB        32
#define NKB       16
#define STAGE     24576
#define GEMM_SMEM (3 * STAGE)   // 73728

// EPI: 0 -> write fp32 C;  1 -> write bf16 hi/lo planes Ch/Cl
template <int EPI>
__device__ __forceinline__ void gemm_nt_bf16(
    const __nv_bfloat16* __restrict__ Ah, const __nv_bfloat16* __restrict__ Al, int lda,
    const __nv_bfloat16* __restrict__ Bh, const __nv_bfloat16* __restrict__ Bl, int ldb,
    float* __restrict__ C, __nv_bfloat16* __restrict__ Ch,
    __nv_bfloat16* __restrict__ Cl, int ldc)
{
    extern __shared__ __align__(128) char smc[];
    const uint32_t sa = smem_u32(smc);

    const int tid = threadIdx.x;
    const int wid = tid >> 5;          // 0..7
    const int lid = tid & 31;
    const int wr  = wid >> 1;          // 0..3 (M)
    const int wc  = wid & 1;           // 0..1 (N)
    const int g   = lid >> 2;
    const int tg  = lid & 3;

    const __nv_bfloat16* Abh = Ah + (size_t)(blockIdx.y * 128) * lda;
    const __nv_bfloat16* Abl = Al + (size_t)(blockIdx.y * 128) * lda;
    const __nv_bfloat16* Bbh = Bh + (size_t)(blockIdx.x * 64) * ldb;
    const __nv_bfloat16* Bbl = Bl + (size_t)(blockIdx.x * 64) * ldb;

    auto load_stage = [&](int buf, int kb) {
        const uint32_t dbase = sa + buf * STAGE;
        const int kc = kb * KB;
#pragma unroll
        for (int i = 0; i < 4; ++i) {               // A: 1024 chunks
            const int t = tid + (i << 8);
            const int row = t >> 3, c = t & 7;
            const __nv_bfloat16* src =
                ((c & 4) ? Abl : Abh) + (size_t)row * lda + kc + (c & 3) * 8;
            cp16(dbase + row * 128 + ((c ^ (row & 7)) << 4), src);
        }
        {                                            // B: 512 chunks
            const int t = tid + 1024;
            const int row = (t >> 3) & 63, c = t & 7;
            const __nv_bfloat16* src =
                ((c & 4) ? Bbl : Bbh) + (size_t)row * ldb + kc + (c & 3) * 8;
            cp16(dbase + 16384 + row * 128 + ((c ^ (row & 7)) << 4), src);
        }
        {
            const int t = tid + 1280;
            const int row = (t >> 3) & 63, c = t & 7;
            const __nv_bfloat16* src =
                ((c & 4) ? Bbl : Bbh) + (size_t)row * ldb + kc + (c & 3) * 8;
            cp16(dbase + 16384 + row * 128 + ((c ^ (row & 7)) << 4), src);
        }
    };

    float acc[2][4][4];
#pragma unroll
    for (int mt = 0; mt < 2; ++mt)
#pragma unroll
        for (int nt = 0; nt < 4; ++nt)
#pragma unroll
            for (int i = 0; i < 4; ++i) acc[mt][nt][i] = 0.0f;

    const uint32_t sx = (uint32_t)(lid & 7) << 4;
    const uint32_t hb = (uint32_t)(lid >> 4) << 4;
    uint32_t ra[2], rb[2];
#pragma unroll
    for (int mt = 0; mt < 2; ++mt)
        ra[mt] = (uint32_t)(wr * 32 + mt * 16 + (lid & 15)) * 128;
#pragma unroll
    for (int n2 = 0; n2 < 2; ++n2)
        rb[n2] = 16384u + (uint32_t)(wc * 32 + n2 * 16 + (lid & 15)) * 128;

    load_stage(0, 0); CP_COMMIT();
    load_stage(1, 1); CP_COMMIT();

#pragma unroll 1
    for (int kb = 0; kb < NKB; ++kb) {
        CP_WAIT1();            // exactly the newest group may be pending
        __syncthreads();
        if (kb + 2 < NKB) load_stage((kb + 2) % 3, kb + 2);
        CP_COMMIT();           // commit every iteration (possibly empty)

        const uint32_t sbase = sa + (kb % 3) * STAGE;

#pragma unroll
        for (int ks = 0; ks < 2; ++ks) {
            const uint32_t cvh = (uint32_t)(ks << 5) + hb;
            const uint32_t cvl = cvh + 64;

            uint32_t ah[2][4], al[2][4], bb[4][2];
#pragma unroll
            for (int mt = 0; mt < 2; ++mt) {
                ldsm4(ah[mt], sbase + ra[mt] + (cvh ^ sx));
                ldsm4(al[mt], sbase + ra[mt] + (cvl ^ sx));
            }
            // ---- B hi ----
#pragma unroll
            for (int n2 = 0; n2 < 2; ++n2) {
                uint32_t r[4];
                ldsm4(r, sbase + rb[n2] + (cvh ^ sx));
                bb[n2 * 2][0] = r[0]; bb[n2 * 2][1] = r[2];
                bb[n2 * 2 + 1][0] = r[1]; bb[n2 * 2 + 1][1] = r[3];
            }
#pragma unroll
            for (int mt = 0; mt < 2; ++mt)
#pragma unroll
                for (int nt = 0; nt < 4; ++nt) mma16(acc[mt][nt], ah[mt], bb[nt]);
#pragma unroll
            for (int mt = 0; mt < 2; ++mt)
#pragma unroll
                for (int nt = 0; nt < 4; ++nt) mma16(acc[mt][nt], al[mt], bb[nt]);
            // ---- B lo (reuse regs) ----
#pragma unroll
            for (int n2 = 0; n2 < 2; ++n2) {
                uint32_t r[4];
                ldsm4(r, sbase + rb[n2] + (cvl ^ sx));
                bb[n2 * 2][0] = r[0]; bb[n2 * 2][1] = r[2];
                bb[n2 * 2 + 1][0] = r[1]; bb[n2 * 2 + 1][1] = r[3];
            }
#pragma unroll
            for (int mt = 0; mt < 2; ++mt)
#pragma unroll
                for (int nt = 0; nt < 4; ++nt) mma16(acc[mt][nt], ah[mt], bb[nt]);
        }
    }

    const int rbase = blockIdx.y * 128 + wr * 32 + g;
    const int cbase = blockIdx.x * 64 + wc * 32 + tg * 2;
#pragma unroll
    for (int mt = 0; mt < 2; ++mt) {
#pragma unroll
        for (int nt = 0; nt < 4; ++nt) {
            const int r = rbase + mt * 16;
            const int c = cbase + nt * 8;
            if (EPI == 0) {
                *reinterpret_cast<float2*>(&C[(size_t)r * ldc + c]) =
                    make_float2(acc[mt][nt][0], acc[mt][nt][1]);
                *reinterpret_cast<float2*>(&C[(size_t)(r + 8) * ldc + c]) =
                    make_float2(acc[mt][nt][2], acc[mt][nt][3]);
            } else {
                uint32_t h, l;
                pack2(acc[mt][nt][0], acc[mt][nt][1], h, l);
                *reinterpret_cast<uint32_t*>(Ch + (size_t)r * ldc + c) = h;
                *reinterpret_cast<uint32_t*>(Cl + (size_t)r * ldc + c) = l;
                pack2(acc[mt][nt][2], acc[mt][nt][3], h, l);
                *reinterpret_cast<uint32_t*>(Ch + (size_t)(r + 8) * ldc + c) = h;
                *reinterpret_cast<uint32_t*>(Cl + (size_t)(r + 8) * ldc + c) = l;
            }
        }
    }
}

// ===========================================================================
// GEMM wrappers
// ===========================================================================
__global__ void __launch_bounds__(256, 3)
proj_mm()
{
    const int z = blockIdx.z;                 // 0:Q 1:K 2:V
    const __nv_bfloat16* Bh = g_WTh + (size_t)z * 4096 * 512;
    const __nv_bfloat16* Bl = g_WTl + (size_t)z * 4096 * 512;
    if (z == 0) {
        gemm_nt_bf16<1>(g_xh, g_xl, 512, Bh, Bl, 512, nullptr, g_Qh, g_Ql, 4096);
    } else if (z == 1) {
        gemm_nt_bf16<1>(g_xh, g_xl, 512, Bh, Bl, 512, nullptr, g_Kh, g_Kl, 4096);
    } else {
        gemm_nt_bf16<0>(g_xh, g_xl, 512, Bh, Bl, 512, g_V, nullptr, nullptr, 4096);
    }
}

__global__ void __launch_bounds__(256, 3)
qk_mm()
{
    const int z = blockIdx.z;                 // h*16 + b
    const int h = z >> 4, b = z & 15;
    const size_t off = (size_t)b * 512 * 4096 + h * 512;
    gemm_nt_bf16<0>(g_Qh + off, g_Ql + off, 4096,
                    g_Kh + off, g_Kl + off, 4096,
                    g_P + (size_t)z * 512 * 512, nullptr, nullptr, 512);
}

__global__ void __launch_bounds__(256, 3)
pv_mm(float* __restrict__ out)
{
    const int z = blockIdx.z;
    const int h = z >> 4, b = z & 15;
    const size_t zo = (size_t)z * 512 * 512;
    gemm_nt_bf16<0>(g_Ph + zo, g_Pl + zo, 512,
                    g_VTh + zo, g_VTl + zo, 512,
                    out + (size_t)b * 512 * 4096 + h * 512, nullptr, nullptr, 4096);
}

// ===========================================================================
// Splits / transposes
// ===========================================================================
__global__ void split_x(const float* __restrict__ x)
{
    const size_t i = ((size_t)blockIdx.x * 256 + threadIdx.x) * 4;
    const float4 v = *reinterpret_cast<const float4*>(x + i);
    uint32_t h0, l0, h1, l1;
    pack2(v.x, v.y, h0, l0);
    pack2(v.z, v.w, h1, l1);
    *reinterpret_cast<uint2*>(g_xh + i) = make_uint2(h0, h1);
    *reinterpret_cast<uint2*>(g_xl + i) = make_uint2(l0, l1);
}

__global__ void wt_kernel(const float* __restrict__ wq,
                          const float* __restrict__ wk,
                          const float* __restrict__ wv, int zbase)
{
    __shared__ float t[32][33];
    const int z = zbase + blockIdx.z;
    const float* W = (z == 0) ? wq : (z == 1) ? wk : wv;   // [512, 4096]
    __nv_bfloat16* WTh = g_WTh + (size_t)z * 4096 * 512;
    __nv_bfloat16* WTl = g_WTl + (size_t)z * 4096 * 512;
    const int n0 = blockIdx.x * 32, k0 = blockIdx.y * 32;
    const int tx = threadIdx.x, ty = threadIdx.y;
#pragma unroll
    for (int i = 0; i < 4; ++i)
        t[ty + i * 8][tx] = W[(size_t)(k0 + ty + i * 8) * 4096 + n0 + tx];
    __syncthreads();
#pragma unroll
    for (int i = 0; i < 4; ++i) {
        const float v = t[tx][ty + i * 8];
        const __nv_bfloat16 hbf = __float2bfloat16_rn(v);
        const float lo = v - __bfloat162float(hbf);
        const size_t idx = (size_t)(n0 + ty + i * 8) * 512 + k0 + tx;
        WTh[idx] = hbf;
        WTl[idx] = __float2bfloat16_rn(lo);
    }
}

__global__ void vt_kernel()
{
    __shared__ float t[32][33];
    const int z = blockIdx.z;                 // h*16 + b
    const int h = z >> 4, b = z & 15;
    const int j0 = blockIdx.x * 32, d0 = blockIdx.y * 32;
    const int tx = threadIdx.x, ty = threadIdx.y;
#pragma unroll
    for (int i = 0; i < 4; ++i)
        t[ty + i * 8][tx] = g_V[(size_t)(b * 512 + j0 + ty + i * 8) * 4096 + h * 512 + d0 + tx];
    __syncthreads();
    __nv_bfloat16* VTh = g_VTh + (size_t)z * 512 * 512;
    __nv_bfloat16* VTl = g_VTl + (size_t)z * 512 * 512;
#pragma unroll
    for (int i = 0; i < 4; ++i) {
        const float v = t[tx][ty + i * 8];
        const __nv_bfloat16 hbf = __float2bfloat16_rn(v);
        const float lo = v - __bfloat162float(hbf);
        const size_t idx = (size_t)(d0 + ty + i * 8) * 512 + j0 + tx;
        VTh[idx] = hbf;
        VTl[idx] = __float2bfloat16_rn(lo);
    }
}

// ===========================================================================
// Softmax over rows of g_P (512 wide), writes bf16 hi/lo planes.
// ===========================================================================
__global__ void softmax_kernel()
{
    const size_t row = blockIdx.x;
    const float* p = g_P + row * 512;
    const int t = threadIdx.x;  // 0..255

    float2 v = reinterpret_cast<const float2*>(p)[t];
    __shared__ float red[8];

    float m = fmaxf(v.x, v.y);
#pragma unroll
    for (int o = 16; o > 0; o >>= 1) m = fmaxf(m, __shfl_xor_sync(0xFFFFFFFFu, m, o));
    if ((t & 31) == 0) red[t >> 5] = m;
    __syncthreads();
    m = red[0];
#pragma unroll
    for (int i = 1; i < 8; i++) m = fmaxf(m, red[i]);
    __syncthreads();

    const float e0 = __expf(v.x - m);
    const float e1 = __expf(v.y - m);

    float s = e0 + e1;
#pragma unroll
    for (int o = 16; o > 0; o >>= 1) s += __shfl_xor_sync(0xFFFFFFFFu, s, o);
    if ((t & 31) == 0) red[t >> 5] = s;
    __syncthreads();
    s = red[0];
#pragma unroll
    for (int i = 1; i < 8; i++) s += red[i];

    const float inv = 1.0f / s;
    uint32_t h, l;
    pack2(e0 * inv, e1 * inv, h, l);
    reinterpret_cast<uint32_t*>(g_Ph + row * 512)[t] = h;
    reinterpret_cast<uint32_t*>(g_Pl + row * 512)[t] = l;
}

// ===========================================================================
// Launch
// ===========================================================================
extern "C" void kernel_launch(void* const* d_in, const int* in_sizes, int n_in,
                              void* d_out, int out_size)
{
    const float* x  = (const float*)d_in[0];
    const float* wq = (const float*)d_in[1];
    const float* wk = (const float*)d_in[2];
    const float* wv = (const float*)d_in[3];
    float* out = (float*)d_out;

    cudaFuncSetAttribute(proj_mm, cudaFuncAttributeMaxDynamicSharedMemorySize, GEMM_SMEM);
    cudaFuncSetAttribute(qk_mm,   cudaFuncAttributeMaxDynamicSharedMemorySize, GEMM_SMEM);
    cudaFuncSetAttribute(pv_mm,   cudaFuncAttributeMaxDynamicSharedMemorySize, GEMM_SMEM);

    split_x<<<4096, 256>>>(x);                                   // 1
    wt_kernel<<<dim3(128, 16, 2), dim3(32, 8)>>>(wq, wk, wv, 0); // 2
    wt_kernel<<<dim3(128, 16, 1), dim3(32, 8)>>>(wq, wk, wv, 2); // 3
    proj_mm<<<dim3(64, 64, 3), 256, GEMM_SMEM>>>();              // 4 <- profiled
    qk_mm<<<dim3(8, 4, 128), 256, GEMM_SMEM>>>();                // 5
    softmax_kernel<<<65536, 256>>>();                            // 6
    vt_kernel<<<dim3(16, 16, 128), dim3(32, 8)>>>();             // 7
    pv_mm<<<dim3(8, 4, 128), 256, GEMM_SMEM>>>(out);             // 8
}

// round 11
// speedup vs baseline: 2.7262x; 1.0743x over previous
#include <cuda_runtime.h>
#include <cuda_bf16.h>
#include <cuda_fp16.h>
#include <cstdint>

// ---------------------------------------------------------------------------
// Problem: B=16, S=512, F=512, H=8, D=512.
// Logit path (proj, qk): bf16 hi/lo 3-term emulation (unchanged from R10).
// PV path: fp16. P = single plane (2^-12 rel), V = fp16 hi/lo 2-pass.
// ---------------------------------------------------------------------------
__device__ float g_V[16 * 512 * 4096];      // V projection fp32 (pre-transpose)
__device__ float g_P[128 * 512 * 512];      // scores fp32 (softmax input)

__device__ __nv_bfloat16 g_xh[8192 * 512],       g_xl[8192 * 512];
__device__ __nv_bfloat16 g_WTh[3 * 4096 * 512],  g_WTl[3 * 4096 * 512];
__device__ __nv_bfloat16 g_Qh[8192 * 4096],      g_Ql[8192 * 4096];
__device__ __nv_bfloat16 g_Kh[8192 * 4096],      g_Kl[8192 * 4096];
__device__ __half        g_VTh[128 * 512 * 512], g_VTl[128 * 512 * 512];
__device__ __half        g_Pf[128 * 512 * 512];  // softmax probs, fp16 single

// ===========================================================================
// Helpers
// ===========================================================================
__device__ __forceinline__ uint32_t smem_u32(const void* p) {
    uint32_t a;
    asm("{ .reg .u64 t; cvta.to.shared.u64 t, %1; cvt.u32.u64 %0, t; }"
        : "=r"(a) : "l"(p));
    return a;
}

__device__ __forceinline__ void cp16(uint32_t dst, const void* src) {
    asm volatile("cp.async.cg.shared.global [%0], [%1], 16;"
                 :: "r"(dst), "l"(src) : "memory");
}
#define CP_COMMIT() asm volatile("cp.async.commit_group;" ::: "memory")
#define CP_WAIT1()  asm volatile("cp.async.wait_group 1;" ::: "memory")

// pack two fp32 into bf16x2 hi-plane word + lo-plane word (rn rounding)
__device__ __forceinline__ void pack2(float x0, float x1, uint32_t& h, uint32_t& l) {
    asm("cvt.rn.bf16x2.f32 %0, %1, %2;" : "=r"(h) : "f"(x1), "f"(x0));
    float f0 = __uint_as_float(h << 16);
    float f1 = __uint_as_float(h & 0xFFFF0000u);
    float l0 = x0 - f0, l1 = x1 - f1;
    asm("cvt.rn.bf16x2.f32 %0, %1, %2;" : "=r"(l) : "f"(l1), "f"(l0));
}

// D += A * B : m16n8k16 bf16, row.col, fp32 accumulate
__device__ __forceinline__ void mma16(float* c, const uint32_t* a, const uint32_t* b) {
    asm volatile(
        "mma.sync.aligned.m16n8k16.row.col.f32.bf16.bf16.f32 "
        "{%0,%1,%2,%3}, {%4,%5,%6,%7}, {%8,%9}, {%0,%1,%2,%3};"
        : "+f"(c[0]), "+f"(c[1]), "+f"(c[2]), "+f"(c[3])
        : "r"(a[0]), "r"(a[1]), "r"(a[2]), "r"(a[3]), "r"(b[0]), "r"(b[1]));
}

// D += A * B : m16n8k16 fp16, row.col, fp32 accumulate
__device__ __forceinline__ void mma16f(float* c, const uint32_t* a, const uint32_t* b) {
    asm volatile(
        "mma.sync.aligned.m16n8k16.row.col.f32.f16.f16.f32 "
        "{%0,%1,%2,%3}, {%4,%5,%6,%7}, {%8,%9}, {%0,%1,%2,%3};"
        : "+f"(c[0]), "+f"(c[1]), "+f"(c[2]), "+f"(c[3])
        : "r"(a[0]), "r"(a[1]), "r"(a[2]), "r"(a[3]), "r"(b[0]), "r"(b[1]));
}

__device__ __forceinline__ void ldsm4(uint32_t* r, uint32_t addr) {
    asm volatile("ldmatrix.sync.aligned.m8n8.x4.shared.b16 {%0,%1,%2,%3}, [%4];"
                 : "=r"(r[0]), "=r"(r[1]), "=r"(r[2]), "=r"(r[3]) : "r"(addr));
}

// ===========================================================================
// NT GEMM on bf16 hi/lo planes (3-term emulation of fp32), 256 threads.
//   [unchanged R10 core: warp tile 32x32, CTA 128x64, 3 CTAs/SM]
// ===========================================================================
#define KB        32
#define NKB       16
#define STAGE     24576
#define GEMM_SMEM (3 * STAGE)   // 73728

template <int EPI>   // 0: fp32 C ; 1: bf16 hi/lo planes
__device__ __forceinline__ void gemm_nt_bf16(
    const __nv_bfloat16* __restrict__ Ah, const __nv_bfloat16* __restrict__ Al, int lda,
    const __nv_bfloat16* __restrict__ Bh, const __nv_bfloat16* __restrict__ Bl, int ldb,
    float* __restrict__ C, __nv_bfloat16* __restrict__ Ch,
    __nv_bfloat16* __restrict__ Cl, int ldc)
{
    extern __shared__ __align__(128) char smc[];
    const uint32_t sa = smem_u32(smc);

    const int tid = threadIdx.x;
    const int wid = tid >> 5;
    const int lid = tid & 31;
    const int wr  = wid >> 1;          // 0..3 (M)
    const int wc  = wid & 1;           // 0..1 (N)
    const int g   = lid >> 2;
    const int tg  = lid & 3;

    const __nv_bfloat16* Abh = Ah + (size_t)(blockIdx.y * 128) * lda;
    const __nv_bfloat16* Abl = Al + (size_t)(blockIdx.y * 128) * lda;
    const __nv_bfloat16* Bbh = Bh + (size_t)(blockIdx.x * 64) * ldb;
    const __nv_bfloat16* Bbl = Bl + (size_t)(blockIdx.x * 64) * ldb;

    auto load_stage = [&](int buf, int kb) {
        const uint32_t dbase = sa + buf * STAGE;
        const int kc = kb * KB;
#pragma unroll
        for (int i = 0; i < 4; ++i) {               // A: 1024 chunks
            const int t = tid + (i << 8);
            const int row = t >> 3, c = t & 7;
            const __nv_bfloat16* src =
                ((c & 4) ? Abl : Abh) + (size_t)row * lda + kc + (c & 3) * 8;
            cp16(dbase + row * 128 + ((c ^ (row & 7)) << 4), src);
        }
        {
            const int t = tid + 1024;
            const int row = (t >> 3) & 63, c = t & 7;
            const __nv_bfloat16* src =
                ((c & 4) ? Bbl : Bbh) + (size_t)row * ldb + kc + (c & 3) * 8;
            cp16(dbase + 16384 + row * 128 + ((c ^ (row & 7)) << 4), src);
        }
        {
            const int t = tid + 1280;
            const int row = (t >> 3) & 63, c = t & 7;
            const __nv_bfloat16* src =
                ((c & 4) ? Bbl : Bbh) + (size_t)row * ldb + kc + (c & 3) * 8;
            cp16(dbase + 16384 + row * 128 + ((c ^ (row & 7)) << 4), src);
        }
    };

    float acc[2][4][4];
#pragma unroll
    for (int mt = 0; mt < 2; ++mt)
#pragma unroll
        for (int nt = 0; nt < 4; ++nt)
#pragma unroll
            for (int i = 0; i < 4; ++i) acc[mt][nt][i] = 0.0f;

    const uint32_t sx = (uint32_t)(lid & 7) << 4;
    const uint32_t hb = (uint32_t)(lid >> 4) << 4;
    uint32_t ra[2], rb[2];
#pragma unroll
    for (int mt = 0; mt < 2; ++mt)
        ra[mt] = (uint32_t)(wr * 32 + mt * 16 + (lid & 15)) * 128;
#pragma unroll
    for (int n2 = 0; n2 < 2; ++n2)
        rb[n2] = 16384u + (uint32_t)(wc * 32 + n2 * 16 + (lid & 15)) * 128;

    load_stage(0, 0); CP_COMMIT();
    load_stage(1, 1); CP_COMMIT();

#pragma unroll 1
    for (int kb = 0; kb < NKB; ++kb) {
        CP_WAIT1();
        __syncthreads();
        if (kb + 2 < NKB) load_stage((kb + 2) % 3, kb + 2);
        CP_COMMIT();

        const uint32_t sbase = sa + (kb % 3) * STAGE;

#pragma unroll
        for (int ks = 0; ks < 2; ++ks) {
            const uint32_t cvh = (uint32_t)(ks << 5) + hb;
            const uint32_t cvl = cvh + 64;

            uint32_t ah[2][4], al[2][4], bb[4][2];
#pragma unroll
            for (int mt = 0; mt < 2; ++mt) {
                ldsm4(ah[mt], sbase + ra[mt] + (cvh ^ sx));
                ldsm4(al[mt], sbase + ra[mt] + (cvl ^ sx));
            }
#pragma unroll
            for (int n2 = 0; n2 < 2; ++n2) {
                uint32_t r[4];
                ldsm4(r, sbase + rb[n2] + (cvh ^ sx));
                bb[n2 * 2][0] = r[0]; bb[n2 * 2][1] = r[2];
                bb[n2 * 2 + 1][0] = r[1]; bb[n2 * 2 + 1][1] = r[3];
            }
#pragma unroll
            for (int mt = 0; mt < 2; ++mt)
#pragma unroll
                for (int nt = 0; nt < 4; ++nt) mma16(acc[mt][nt], ah[mt], bb[nt]);
#pragma unroll
            for (int mt = 0; mt < 2; ++mt)
#pragma unroll
                for (int nt = 0; nt < 4; ++nt) mma16(acc[mt][nt], al[mt], bb[nt]);
#pragma unroll
            for (int n2 = 0; n2 < 2; ++n2) {
                uint32_t r[4];
                ldsm4(r, sbase + rb[n2] + (cvl ^ sx));
                bb[n2 * 2][0] = r[0]; bb[n2 * 2][1] = r[2];
                bb[n2 * 2 + 1][0] = r[1]; bb[n2 * 2 + 1][1] = r[3];
            }
#pragma unroll
            for (int mt = 0; mt < 2; ++mt)
#pragma unroll
                for (int nt = 0; nt < 4; ++nt) mma16(acc[mt][nt], ah[mt], bb[nt]);
        }
    }

    const int rbase = blockIdx.y * 128 + wr * 32 + g;
    const int cbase = blockIdx.x * 64 + wc * 32 + tg * 2;
#pragma unroll
    for (int mt = 0; mt < 2; ++mt) {
#pragma unroll
        for (int nt = 0; nt < 4; ++nt) {
            const int r = rbase + mt * 16;
            const int c = cbase + nt * 8;
            if (EPI == 0) {
                *reinterpret_cast<float2*>(&C[(size_t)r * ldc + c]) =
                    make_float2(acc[mt][nt][0], acc[mt][nt][1]);
                *reinterpret_cast<float2*>(&C[(size_t)(r + 8) * ldc + c]) =
                    make_float2(acc[mt][nt][2], acc[mt][nt][3]);
            } else {
                uint32_t h, l;
                pack2(acc[mt][nt][0], acc[mt][nt][1], h, l);
                *reinterpret_cast<uint32_t*>(Ch + (size_t)r * ldc + c) = h;
                *reinterpret_cast<uint32_t*>(Cl + (size_t)r * ldc + c) = l;
                pack2(acc[mt][nt][2], acc[mt][nt][3], h, l);
                *reinterpret_cast<uint32_t*>(Ch + (size_t)(r + 8) * ldc + c) = h;
                *reinterpret_cast<uint32_t*>(Cl + (size_t)(r + 8) * ldc + c) = l;
            }
        }
    }
}

// ===========================================================================
// GEMM wrappers (logit path, unchanged)
// ===========================================================================
__global__ void __launch_bounds__(256, 3)
proj_mm()
{
    const int z = blockIdx.z;                 // 0:Q 1:K 2:V
    const __nv_bfloat16* Bh = g_WTh + (size_t)z * 4096 * 512;
    const __nv_bfloat16* Bl = g_WTl + (size_t)z * 4096 * 512;
    if (z == 0) {
        gemm_nt_bf16<1>(g_xh, g_xl, 512, Bh, Bl, 512, nullptr, g_Qh, g_Ql, 4096);
    } else if (z == 1) {
        gemm_nt_bf16<1>(g_xh, g_xl, 512, Bh, Bl, 512, nullptr, g_Kh, g_Kl, 4096);
    } else {
        gemm_nt_bf16<0>(g_xh, g_xl, 512, Bh, Bl, 512, g_V, nullptr, nullptr, 4096);
    }
}

__global__ void __launch_bounds__(256, 3)
qk_mm()
{
    const int z = blockIdx.z;                 // h*16 + b
    const int h = z >> 4, b = z & 15;
    const size_t off = (size_t)b * 512 * 4096 + h * 512;
    gemm_nt_bf16<0>(g_Qh + off, g_Ql + off, 4096,
                    g_Kh + off, g_Kl + off, 4096,
                    g_P + (size_t)z * 512 * 512, nullptr, nullptr, 512);
}

// ===========================================================================
// PV GEMM: fp16, 2 passes (P single plane x V hi/lo), 256 threads.
//   C[128x64] = P[128,512] @ VT[64,512]^T
// 8 warps 4(M)x2(N), warp tile 32x32. KB=64 (full 128B row per plane).
// Stage 32KB: P rows 0..127 @ [0,16K), VTh 64 rows @ [16K,24K), VTl @ [24K,32K).
// 3-stage ring, 2 CTAs/SM.
// ===========================================================================
#define PV_STAGE 32768
#define PV_SMEM  (3 * PV_STAGE)   // 98304

__global__ void __launch_bounds__(256, 2)
pv_mm(float* __restrict__ out)
{
    extern __shared__ __align__(128) char smc[];
    const uint32_t sa = smem_u32(smc);

    const int z = blockIdx.z;
    const int h = z >> 4, b = z & 15;
    const size_t zo = (size_t)z * 262144;

    const __half* Ab  = g_Pf  + zo + (size_t)(blockIdx.y * 128) * 512;
    const __half* Bhb = g_VTh + zo + (size_t)(blockIdx.x * 64) * 512;
    const __half* Blb = g_VTl + zo + (size_t)(blockIdx.x * 64) * 512;
    float* C = out + (size_t)b * 512 * 4096 + h * 512;

    const int tid = threadIdx.x;
    const int wid = tid >> 5;
    const int lid = tid & 31;
    const int wr  = wid >> 1;          // 0..3 (M)
    const int wc  = wid & 1;           // 0..1 (N)
    const int g   = lid >> 2;
    const int tg  = lid & 3;

    auto load_stage = [&](int buf, int kb) {
        const uint32_t dbase = sa + buf * PV_STAGE;
        const int kc = kb * 64;
#pragma unroll
        for (int i = 0; i < 4; ++i) {               // P: 1024 chunks
            const int t = tid + (i << 8);
            const int row = t >> 3, c = t & 7;
            cp16(dbase + row * 128 + ((c ^ (row & 7)) << 4),
                 Ab + (size_t)row * 512 + kc + c * 8);
        }
#pragma unroll
        for (int i = 0; i < 4; ++i) {               // VTh+VTl: 1024 chunks
            const int t = tid + (i << 8);
            const int pl = t >> 9, row = (t >> 3) & 63, c = t & 7;
            const __half* src = (pl ? Blb : Bhb) + (size_t)row * 512 + kc + c * 8;
            cp16(dbase + 16384 + pl * 8192 + row * 128 + ((c ^ (row & 7)) << 4), src);
        }
    };

    float acc[2][4][4];
#pragma unroll
    for (int mt = 0; mt < 2; ++mt)
#pragma unroll
        for (int nt = 0; nt < 4; ++nt)
#pragma unroll
            for (int i = 0; i < 4; ++i) acc[mt][nt][i] = 0.0f;

    const uint32_t sx = (uint32_t)(lid & 7) << 4;
    const uint32_t hb = (uint32_t)(lid >> 4) << 4;
    uint32_t ra[2], rb[2];
#pragma unroll
    for (int mt = 0; mt < 2; ++mt)
        ra[mt] = (uint32_t)(wr * 32 + mt * 16 + (lid & 15)) * 128;
#pragma unroll
    for (int n2 = 0; n2 < 2; ++n2)
        rb[n2] = 16384u + (uint32_t)(wc * 32 + n2 * 16 + (lid & 15)) * 128;

    load_stage(0, 0); CP_COMMIT();
    load_stage(1, 1); CP_COMMIT();

#pragma unroll 1
    for (int kb = 0; kb < 8; ++kb) {               // NKB = 512/64 = 8
        CP_WAIT1();
        __syncthreads();
        if (kb + 2 < 8) load_stage((kb + 2) % 3, kb + 2);
        CP_COMMIT();

        const uint32_t sbase = sa + (kb % 3) * PV_STAGE;

#pragma unroll
        for (int ks = 0; ks < 4; ++ks) {           // 4 x k16 per 64-k block
            const uint32_t cv = (uint32_t)(ks << 5) + hb;

            uint32_t ah[2][4], bb[4][2];
#pragma unroll
            for (int mt = 0; mt < 2; ++mt)
                ldsm4(ah[mt], sbase + ra[mt] + (cv ^ sx));
            // ---- V hi ----
#pragma unroll
            for (int n2 = 0; n2 < 2; ++n2) {
                uint32_t r[4];
                ldsm4(r, sbase + rb[n2] + (cv ^ sx));
                bb[n2 * 2][0] = r[0]; bb[n2 * 2][1] = r[2];
                bb[n2 * 2 + 1][0] = r[1]; bb[n2 * 2 + 1][1] = r[3];
            }
#pragma unroll
            for (int mt = 0; mt < 2; ++mt)
#pragma unroll
                for (int nt = 0; nt < 4; ++nt) mma16f(acc[mt][nt], ah[mt], bb[nt]);
            // ---- V lo ----
#pragma unroll
            for (int n2 = 0; n2 < 2; ++n2) {
                uint32_t r[4];
                ldsm4(r, sbase + rb[n2] + 8192 + (cv ^ sx));
                bb[n2 * 2][0] = r[0]; bb[n2 * 2][1] = r[2];
                bb[n2 * 2 + 1][0] = r[1]; bb[n2 * 2 + 1][1] = r[3];
            }
#pragma unroll
            for (int mt = 0; mt < 2; ++mt)
#pragma unroll
                for (int nt = 0; nt < 4; ++nt) mma16f(acc[mt][nt], ah[mt], bb[nt]);
        }
    }

    const int rbase = blockIdx.y * 128 + wr * 32 + g;
    const int cbase = blockIdx.x * 64 + wc * 32 + tg * 2;
#pragma unroll
    for (int mt = 0; mt < 2; ++mt) {
#pragma unroll
        for (int nt = 0; nt < 4; ++nt) {
            const int r = rbase + mt * 16;
            const int c = cbase + nt * 8;
            *reinterpret_cast<float2*>(&C[(size_t)r * 4096 + c]) =
                make_float2(acc[mt][nt][0], acc[mt][nt][1]);
            *reinterpret_cast<float2*>(&C[(size_t)(r + 8) * 4096 + c]) =
                make_float2(acc[mt][nt][2], acc[mt][nt][3]);
        }
    }
}

// ===========================================================================
// Splits / transposes
// ===========================================================================
__global__ void split_x(const float* __restrict__ x)
{
    const size_t i = ((size_t)blockIdx.x * 256 + threadIdx.x) * 4;
    const float4 v = *reinterpret_cast<const float4*>(x + i);
    uint32_t h0, l0, h1, l1;
    pack2(v.x, v.y, h0, l0);
    pack2(v.z, v.w, h1, l1);
    *reinterpret_cast<uint2*>(g_xh + i) = make_uint2(h0, h1);
    *reinterpret_cast<uint2*>(g_xl + i) = make_uint2(l0, l1);
}

__global__ void wt_kernel(const float* __restrict__ wq,
                          const float* __restrict__ wk,
                          const float* __restrict__ wv, int zbase)
{
    __shared__ float t[32][33];
    const int z = zbase + blockIdx.z;
    const float* W = (z == 0) ? wq : (z == 1) ? wk : wv;   // [512, 4096]
    __nv_bfloat16* WTh = g_WTh + (size_t)z * 4096 * 512;
    __nv_bfloat16* WTl = g_WTl + (size_t)z * 4096 * 512;
    const int n0 = blockIdx.x * 32, k0 = blockIdx.y * 32;
    const int tx = threadIdx.x, ty = threadIdx.y;
#pragma unroll
    for (int i = 0; i < 4; ++i)
        t[ty + i * 8][tx] = W[(size_t)(k0 + ty + i * 8) * 4096 + n0 + tx];
    __syncthreads();
#pragma unroll
    for (int i = 0; i < 4; ++i) {
        const float v = t[tx][ty + i * 8];
        const __nv_bfloat16 hbf = __float2bfloat16_rn(v);
        const float lo = v - __bfloat162float(hbf);
        const size_t idx = (size_t)(n0 + ty + i * 8) * 512 + k0 + tx;
        WTh[idx] = hbf;
        WTl[idx] = __float2bfloat16_rn(lo);
    }
}

__global__ void vt_kernel()
{
    __shared__ float t[32][33];
    const int z = blockIdx.z;                 // h*16 + b
    const int h = z >> 4, b = z & 15;
    const int j0 = blockIdx.x * 32, d0 = blockIdx.y * 32;
    const int tx = threadIdx.x, ty = threadIdx.y;
#pragma unroll
    for (int i = 0; i < 4; ++i)
        t[ty + i * 8][tx] = g_V[(size_t)(b * 512 + j0 + ty + i * 8) * 4096 + h * 512 + d0 + tx];
    __syncthreads();
    __half* VTh = g_VTh + (size_t)z * 512 * 512;
    __half* VTl = g_VTl + (size_t)z * 512 * 512;
#pragma unroll
    for (int i = 0; i < 4; ++i) {
        const float v = t[tx][ty + i * 8];
        const __half hf = __float2half_rn(v);
        const float lo = v - __half2float(hf);
        const size_t idx = (size_t)(d0 + ty + i * 8) * 512 + j0 + tx;
        VTh[idx] = hf;
        VTl[idx] = __float2half_rn(lo);
    }
}

// ===========================================================================
// Softmax over rows of g_P (512 wide), writes single fp16 plane g_Pf.
// ===========================================================================
__global__ void softmax_kernel()
{
    const size_t row = blockIdx.x;
    const float* p = g_P + row * 512;
    const int t = threadIdx.x;  // 0..255

    float2 v = reinterpret_cast<const float2*>(p)[t];
    __shared__ float red[8];

    float m = fmaxf(v.x, v.y);
#pragma unroll
    for (int o = 16; o > 0; o >>= 1) m = fmaxf(m, __shfl_xor_sync(0xFFFFFFFFu, m, o));
    if ((t & 31) == 0) red[t >> 5] = m;
    __syncthreads();
    m = red[0];
#pragma unroll
    for (int i = 1; i < 8; i++) m = fmaxf(m, red[i]);
    __syncthreads();

    const float e0 = __expf(v.x - m);
    const float e1 = __expf(v.y - m);

    float s = e0 + e1;
#pragma unroll
    for (int o = 16; o > 0; o >>= 1) s += __shfl_xor_sync(0xFFFFFFFFu, s, o);
    if ((t & 31) == 0) red[t >> 5] = s;
    __syncthreads();
    s = red[0];
#pragma unroll
    for (int i = 1; i < 8; i++) s += red[i];

    const float inv = 1.0f / s;
    reinterpret_cast<__half2*>(g_Pf + row * 512)[t] =
        __floats2half2_rn(e0 * inv, e1 * inv);
}

// ===========================================================================
// Launch
// ===========================================================================
extern "C" void kernel_launch(void* const* d_in, const int* in_sizes, int n_in,
                              void* d_out, int out_size)
{
    const float* x  = (const float*)d_in[0];
    const float* wq = (const float*)d_in[1];
    const float* wk = (const float*)d_in[2];
    const float* wv = (const float*)d_in[3];
    float* out = (float*)d_out;

    cudaFuncSetAttribute(proj_mm, cudaFuncAttributeMaxDynamicSharedMemorySize, GEMM_SMEM);
    cudaFuncSetAttribute(qk_mm,   cudaFuncAttributeMaxDynamicSharedMemorySize, GEMM_SMEM);
    cudaFuncSetAttribute(pv_mm,   cudaFuncAttributeMaxDynamicSharedMemorySize, PV_SMEM);

    split_x<<<4096, 256>>>(x);                                   // 1
    wt_kernel<<<dim3(128, 16, 2), dim3(32, 8)>>>(wq, wk, wv, 0); // 2
    wt_kernel<<<dim3(128, 16, 1), dim3(32, 8)>>>(wq, wk, wv, 2); // 3
    proj_mm<<<dim3(64, 64, 3), 256, GEMM_SMEM>>>();              // 4 <- profiled
    qk_mm<<<dim3(8, 4, 128), 256, GEMM_SMEM>>>();                // 5
    softmax_kernel<<<65536, 256>>>();                            // 6
    vt_kernel<<<dim3(16, 16, 128), dim3(32, 8)>>>();             // 7
    pv_mm<<<dim3(8, 4, 128), 256, PV_SMEM>>>(out);               // 8
}

// round 12
// speedup vs baseline: 3.0976x; 1.1362x over previous
#include <cuda_runtime.h>
#include <cuda_bf16.h>
#include <cuda_fp16.h>
#include <cstdint>

// ---------------------------------------------------------------------------
// Problem: B=16, S=512, F=512, H=8, D=512.
// Logit path (Q,K proj; qk): bf16 hi/lo 3-term emulation (unchanged).
// V path: V-proj = fp16 2-term (x_hi x (wv_hi + wv_lo)); V stored single fp16;
// PV = single fp16 plane P x single fp16 plane V, 1 MMA pass.
// ---------------------------------------------------------------------------
__device__ float g_V[16 * 512 * 4096];      // V projection fp32 (pre-transpose)
__device__ float g_P[128 * 512 * 512];      // scores fp32 (softmax input)

__device__ __nv_bfloat16 g_xh[8192 * 512],      g_xl[8192 * 512];
__device__ __nv_bfloat16 g_WTh[2 * 4096 * 512], g_WTl[2 * 4096 * 512]; // wq,wk
__device__ __nv_bfloat16 g_Qh[8192 * 4096],     g_Ql[8192 * 4096];
__device__ __nv_bfloat16 g_Kh[8192 * 4096],     g_Kl[8192 * 4096];

__device__ __half g_x16[8192 * 512];                 // x, single fp16 plane
__device__ __half g_WVh[4096 * 512], g_WVl[4096 * 512]; // wv^T fp16 planes
__device__ __half g_VT[128 * 512 * 512];             // V^T single fp16 plane
__device__ __half g_Pf[128 * 512 * 512];             // softmax probs fp16

// ===========================================================================
// Helpers
// ===========================================================================
__device__ __forceinline__ uint32_t smem_u32(const void* p) {
    uint32_t a;
    asm("{ .reg .u64 t; cvta.to.shared.u64 t, %1; cvt.u32.u64 %0, t; }"
        : "=r"(a) : "l"(p));
    return a;
}

__device__ __forceinline__ void cp16(uint32_t dst, const void* src) {
    asm volatile("cp.async.cg.shared.global [%0], [%1], 16;"
                 :: "r"(dst), "l"(src) : "memory");
}
#define CP_COMMIT() asm volatile("cp.async.commit_group;" ::: "memory")
#define CP_WAIT1()  asm volatile("cp.async.wait_group 1;" ::: "memory")

// pack two fp32 into bf16x2 hi-plane word + lo-plane word (rn rounding)
__device__ __forceinline__ void pack2(float x0, float x1, uint32_t& h, uint32_t& l) {
    asm("cvt.rn.bf16x2.f32 %0, %1, %2;" : "=r"(h) : "f"(x1), "f"(x0));
    float f0 = __uint_as_float(h << 16);
    float f1 = __uint_as_float(h & 0xFFFF0000u);
    float l0 = x0 - f0, l1 = x1 - f1;
    asm("cvt.rn.bf16x2.f32 %0, %1, %2;" : "=r"(l) : "f"(l1), "f"(l0));
}

// D += A * B : m16n8k16 bf16, row.col, fp32 accumulate
__device__ __forceinline__ void mma16(float* c, const uint32_t* a, const uint32_t* b) {
    asm volatile(
        "mma.sync.aligned.m16n8k16.row.col.f32.bf16.bf16.f32 "
        "{%0,%1,%2,%3}, {%4,%5,%6,%7}, {%8,%9}, {%0,%1,%2,%3};"
        : "+f"(c[0]), "+f"(c[1]), "+f"(c[2]), "+f"(c[3])
        : "r"(a[0]), "r"(a[1]), "r"(a[2]), "r"(a[3]), "r"(b[0]), "r"(b[1]));
}

// D += A * B : m16n8k16 fp16, row.col, fp32 accumulate
__device__ __forceinline__ void mma16f(float* c, const uint32_t* a, const uint32_t* b) {
    asm volatile(
        "mma.sync.aligned.m16n8k16.row.col.f32.f16.f16.f32 "
        "{%0,%1,%2,%3}, {%4,%5,%6,%7}, {%8,%9}, {%0,%1,%2,%3};"
        : "+f"(c[0]), "+f"(c[1]), "+f"(c[2]), "+f"(c[3])
        : "r"(a[0]), "r"(a[1]), "r"(a[2]), "r"(a[3]), "r"(b[0]), "r"(b[1]));
}

__device__ __forceinline__ void ldsm4(uint32_t* r, uint32_t addr) {
    asm volatile("ldmatrix.sync.aligned.m8n8.x4.shared.b16 {%0,%1,%2,%3}, [%4];"
                 : "=r"(r[0]), "=r"(r[1]), "=r"(r[2]), "=r"(r[3]) : "r"(addr));
}

// ===========================================================================
// NT GEMM on bf16 hi/lo planes (3-term emulation), 256 threads. [R10 core]
//   C[128x64] tile, 8 warps 4(M)x2(N), warp tile 32x32, 3 CTAs/SM.
// ===========================================================================
#define KB        32
#define NKB       16
#define STAGE     24576
#define GEMM_SMEM (3 * STAGE)   // 73728

template <int EPI>   // 0: fp32 C ; 1: bf16 hi/lo planes
__device__ __forceinline__ void gemm_nt_bf16(
    const __nv_bfloat16* __restrict__ Ah, const __nv_bfloat16* __restrict__ Al, int lda,
    const __nv_bfloat16* __restrict__ Bh, const __nv_bfloat16* __restrict__ Bl, int ldb,
    float* __restrict__ C, __nv_bfloat16* __restrict__ Ch,
    __nv_bfloat16* __restrict__ Cl, int ldc)
{
    extern __shared__ __align__(128) char smc[];
    const uint32_t sa = smem_u32(smc);

    const int tid = threadIdx.x;
    const int wid = tid >> 5;
    const int lid = tid & 31;
    const int wr  = wid >> 1;          // 0..3 (M)
    const int wc  = wid & 1;           // 0..1 (N)
    const int g   = lid >> 2;
    const int tg  = lid & 3;

    const __nv_bfloat16* Abh = Ah + (size_t)(blockIdx.y * 128) * lda;
    const __nv_bfloat16* Abl = Al + (size_t)(blockIdx.y * 128) * lda;
    const __nv_bfloat16* Bbh = Bh + (size_t)(blockIdx.x * 64) * ldb;
    const __nv_bfloat16* Bbl = Bl + (size_t)(blockIdx.x * 64) * ldb;

    auto load_stage = [&](int buf, int kb) {
        const uint32_t dbase = sa + buf * STAGE;
        const int kc = kb * KB;
#pragma unroll
        for (int i = 0; i < 4; ++i) {               // A: 1024 chunks
            const int t = tid + (i << 8);
            const int row = t >> 3, c = t & 7;
            const __nv_bfloat16* src =
                ((c & 4) ? Abl : Abh) + (size_t)row * lda + kc + (c & 3) * 8;
            cp16(dbase + row * 128 + ((c ^ (row & 7)) << 4), src);
        }
        {
            const int t = tid + 1024;
            const int row = (t >> 3) & 63, c = t & 7;
            const __nv_bfloat16* src =
                ((c & 4) ? Bbl : Bbh) + (size_t)row * ldb + kc + (c & 3) * 8;
            cp16(dbase + 16384 + row * 128 + ((c ^ (row & 7)) << 4), src);
        }
        {
            const int t = tid + 1280;
            const int row = (t >> 3) & 63, c = t & 7;
            const __nv_bfloat16* src =
                ((c & 4) ? Bbl : Bbh) + (size_t)row * ldb + kc + (c & 3) * 8;
            cp16(dbase + 16384 + row * 128 + ((c ^ (row & 7)) << 4), src);
        }
    };

    float acc[2][4][4];
#pragma unroll
    for (int mt = 0; mt < 2; ++mt)
#pragma unroll
        for (int nt = 0; nt < 4; ++nt)
#pragma unroll
            for (int i = 0; i < 4; ++i) acc[mt][nt][i] = 0.0f;

    const uint32_t sx = (uint32_t)(lid & 7) << 4;
    const uint32_t hb = (uint32_t)(lid >> 4) << 4;
    uint32_t ra[2], rb[2];
#pragma unroll
    for (int mt = 0; mt < 2; ++mt)
        ra[mt] = (uint32_t)(wr * 32 + mt * 16 + (lid & 15)) * 128;
#pragma unroll
    for (int n2 = 0; n2 < 2; ++n2)
        rb[n2] = 16384u + (uint32_t)(wc * 32 + n2 * 16 + (lid & 15)) * 128;

    load_stage(0, 0); CP_COMMIT();
    load_stage(1, 1); CP_COMMIT();

#pragma unroll 1
    for (int kb = 0; kb < NKB; ++kb) {
        CP_WAIT1();
        __syncthreads();
        if (kb + 2 < NKB) load_stage((kb + 2) % 3, kb + 2);
        CP_COMMIT();

        const uint32_t sbase = sa + (kb % 3) * STAGE;

#pragma unroll
        for (int ks = 0; ks < 2; ++ks) {
            const uint32_t cvh = (uint32_t)(ks << 5) + hb;
            const uint32_t cvl = cvh + 64;

            uint32_t ah[2][4], al[2][4], bb[4][2];
#pragma unroll
            for (int mt = 0; mt < 2; ++mt) {
                ldsm4(ah[mt], sbase + ra[mt] + (cvh ^ sx));
                ldsm4(al[mt], sbase + ra[mt] + (cvl ^ sx));
            }
#pragma unroll
            for (int n2 = 0; n2 < 2; ++n2) {
                uint32_t r[4];
                ldsm4(r, sbase + rb[n2] + (cvh ^ sx));
                bb[n2 * 2][0] = r[0]; bb[n2 * 2][1] = r[2];
                bb[n2 * 2 + 1][0] = r[1]; bb[n2 * 2 + 1][1] = r[3];
            }
#pragma unroll
            for (int mt = 0; mt < 2; ++mt)
#pragma unroll
                for (int nt = 0; nt < 4; ++nt) mma16(acc[mt][nt], ah[mt], bb[nt]);
#pragma unroll
            for (int mt = 0; mt < 2; ++mt)
#pragma unroll
                for (int nt = 0; nt < 4; ++nt) mma16(acc[mt][nt], al[mt], bb[nt]);
#pragma unroll
            for (int n2 = 0; n2 < 2; ++n2) {
                uint32_t r[4];
                ldsm4(r, sbase + rb[n2] + (cvl ^ sx));
                bb[n2 * 2][0] = r[0]; bb[n2 * 2][1] = r[2];
                bb[n2 * 2 + 1][0] = r[1]; bb[n2 * 2 + 1][1] = r[3];
            }
#pragma unroll
            for (int mt = 0; mt < 2; ++mt)
#pragma unroll
                for (int nt = 0; nt < 4; ++nt) mma16(acc[mt][nt], ah[mt], bb[nt]);
        }
    }

    const int rbase = blockIdx.y * 128 + wr * 32 + g;
    const int cbase = blockIdx.x * 64 + wc * 32 + tg * 2;
#pragma unroll
    for (int mt = 0; mt < 2; ++mt) {
#pragma unroll
        for (int nt = 0; nt < 4; ++nt) {
            const int r = rbase + mt * 16;
            const int c = cbase + nt * 8;
            if (EPI == 0) {
                *reinterpret_cast<float2*>(&C[(size_t)r * ldc + c]) =
                    make_float2(acc[mt][nt][0], acc[mt][nt][1]);
                *reinterpret_cast<float2*>(&C[(size_t)(r + 8) * ldc + c]) =
                    make_float2(acc[mt][nt][2], acc[mt][nt][3]);
            } else {
                uint32_t h, l;
                pack2(acc[mt][nt][0], acc[mt][nt][1], h, l);
                *reinterpret_cast<uint32_t*>(Ch + (size_t)r * ldc + c) = h;
                *reinterpret_cast<uint32_t*>(Cl + (size_t)r * ldc + c) = l;
                pack2(acc[mt][nt][2], acc[mt][nt][3], h, l);
                *reinterpret_cast<uint32_t*>(Ch + (size_t)(r + 8) * ldc + c) = h;
                *reinterpret_cast<uint32_t*>(Cl + (size_t)(r + 8) * ldc + c) = l;
            }
        }
    }
}

// ===========================================================================
// Q,K projections (bf16 3-term)
// ===========================================================================
__global__ void __launch_bounds__(256, 3)
proj_mm()
{
    const int z = blockIdx.z;                 // 0:Q 1:K
    const __nv_bfloat16* Bh = g_WTh + (size_t)z * 4096 * 512;
    const __nv_bfloat16* Bl = g_WTl + (size_t)z * 4096 * 512;
    if (z == 0)
        gemm_nt_bf16<1>(g_xh, g_xl, 512, Bh, Bl, 512, nullptr, g_Qh, g_Ql, 4096);
    else
        gemm_nt_bf16<1>(g_xh, g_xl, 512, Bh, Bl, 512, nullptr, g_Kh, g_Kl, 4096);
}

__global__ void __launch_bounds__(256, 3)
qk_mm()
{
    const int z = blockIdx.z;                 // h*16 + b
    const int h = z >> 4, b = z & 15;
    const size_t off = (size_t)b * 512 * 4096 + h * 512;
    gemm_nt_bf16<0>(g_Qh + off, g_Ql + off, 4096,
                    g_Kh + off, g_Kl + off, 4096,
                    g_P + (size_t)z * 512 * 512, nullptr, nullptr, 512);
}

// ===========================================================================
// V projection: fp16 2-term. C[128x64] = x_hi[8192,512] @ (wvh+wvl)[4096,512]^T
// KB=64 (A single plane: full 128B row = 64 k). Stage 32K:
//   A 128 rows @ [0,16K), Bh 64 rows @ [16K,24K), Bl @ [24K,32K).
// 3-stage ring, 2 CTAs/SM. NKB = 8.
// ===========================================================================
#define PJV_STAGE 32768
#define PJV_SMEM  (3 * PJV_STAGE)   // 98304

__global__ void __launch_bounds__(256, 2)
proj_v()
{
    extern __shared__ __align__(128) char smc[];
    const uint32_t sa = smem_u32(smc);

    const __half* Ab  = g_x16 + (size_t)(blockIdx.y * 128) * 512;
    const __half* Bhb = g_WVh + (size_t)(blockIdx.x * 64) * 512;
    const __half* Blb = g_WVl + (size_t)(blockIdx.x * 64) * 512;
    float* C = g_V;

    const int tid = threadIdx.x;
    const int wid = tid >> 5;
    const int lid = tid & 31;
    const int wr  = wid >> 1;
    const int wc  = wid & 1;
    const int g   = lid >> 2;
    const int tg  = lid & 3;

    auto load_stage = [&](int buf, int kb) {
        const uint32_t dbase = sa + buf * PJV_STAGE;
        const int kc = kb * 64;
#pragma unroll
        for (int i = 0; i < 4; ++i) {               // A: 1024 chunks
            const int t = tid + (i << 8);
            const int row = t >> 3, c = t & 7;
            cp16(dbase + row * 128 + ((c ^ (row & 7)) << 4),
                 Ab + (size_t)row * 512 + kc + c * 8);
        }
#pragma unroll
        for (int i = 0; i < 4; ++i) {               // Bh+Bl: 1024 chunks
            const int t = tid + (i << 8);
            const int pl = t >> 9, row = (t >> 3) & 63, c = t & 7;
            const __half* src = (pl ? Blb : Bhb) + (size_t)row * 512 + kc + c * 8;
            cp16(dbase + 16384 + pl * 8192 + row * 128 + ((c ^ (row & 7)) << 4), src);
        }
    };

    float acc[2][4][4];
#pragma unroll
    for (int mt = 0; mt < 2; ++mt)
#pragma unroll
        for (int nt = 0; nt < 4; ++nt)
#pragma unroll
            for (int i = 0; i < 4; ++i) acc[mt][nt][i] = 0.0f;

    const uint32_t sx = (uint32_t)(lid & 7) << 4;
    const uint32_t hb = (uint32_t)(lid >> 4) << 4;
    uint32_t ra[2], rb[2];
#pragma unroll
    for (int mt = 0; mt < 2; ++mt)
        ra[mt] = (uint32_t)(wr * 32 + mt * 16 + (lid & 15)) * 128;
#pragma unroll
    for (int n2 = 0; n2 < 2; ++n2)
        rb[n2] = 16384u + (uint32_t)(wc * 32 + n2 * 16 + (lid & 15)) * 128;

    load_stage(0, 0); CP_COMMIT();
    load_stage(1, 1); CP_COMMIT();

#pragma unroll 1
    for (int kb = 0; kb < 8; ++kb) {
        CP_WAIT1();
        __syncthreads();
        if (kb + 2 < 8) load_stage((kb + 2) % 3, kb + 2);
        CP_COMMIT();

        const uint32_t sbase = sa + (kb % 3) * PJV_STAGE;

#pragma unroll
        for (int ks = 0; ks < 4; ++ks) {
            const uint32_t cv = (uint32_t)(ks << 5) + hb;

            uint32_t ah[2][4], bb[4][2];
#pragma unroll
            for (int mt = 0; mt < 2; ++mt)
                ldsm4(ah[mt], sbase + ra[mt] + (cv ^ sx));
            // ---- W hi ----
#pragma unroll
            for (int n2 = 0; n2 < 2; ++n2) {
                uint32_t r[4];
                ldsm4(r, sbase + rb[n2] + (cv ^ sx));
                bb[n2 * 2][0] = r[0]; bb[n2 * 2][1] = r[2];
                bb[n2 * 2 + 1][0] = r[1]; bb[n2 * 2 + 1][1] = r[3];
            }
#pragma unroll
            for (int mt = 0; mt < 2; ++mt)
#pragma unroll
                for (int nt = 0; nt < 4; ++nt) mma16f(acc[mt][nt], ah[mt], bb[nt]);
            // ---- W lo ----
#pragma unroll
            for (int n2 = 0; n2 < 2; ++n2) {
                uint32_t r[4];
                ldsm4(r, sbase + rb[n2] + 8192 + (cv ^ sx));
                bb[n2 * 2][0] = r[0]; bb[n2 * 2][1] = r[2];
                bb[n2 * 2 + 1][0] = r[1]; bb[n2 * 2 + 1][1] = r[3];
            }
#pragma unroll
            for (int mt = 0; mt < 2; ++mt)
#pragma unroll
                for (int nt = 0; nt < 4; ++nt) mma16f(acc[mt][nt], ah[mt], bb[nt]);
        }
    }

    const int rbase = blockIdx.y * 128 + wr * 32 + g;
    const int cbase = blockIdx.x * 64 + wc * 32 + tg * 2;
#pragma unroll
    for (int mt = 0; mt < 2; ++mt) {
#pragma unroll
        for (int nt = 0; nt < 4; ++nt) {
            const int r = rbase + mt * 16;
            const int c = cbase + nt * 8;
            *reinterpret_cast<float2*>(&C[(size_t)r * 4096 + c]) =
                make_float2(acc[mt][nt][0], acc[mt][nt][1]);
            *reinterpret_cast<float2*>(&C[(size_t)(r + 8) * 4096 + c]) =
                make_float2(acc[mt][nt][2], acc[mt][nt][3]);
        }
    }
}

// ===========================================================================
// PV GEMM: single fp16 P x single fp16 V, 1 MMA pass. C[128x64] fp32.
// KB=64. Stage 24K: P 128 rows @ [0,16K), V 64 rows @ [16K,24K).
// 3-stage ring, 3 CTAs/SM. NKB=8.
// ===========================================================================
#define PV_STAGE 24576
#define PV_SMEM  (3 * PV_STAGE)   // 73728

__global__ void __launch_bounds__(256, 3)
pv_mm(float* __restrict__ out)
{
    extern __shared__ __align__(128) char smc[];
    const uint32_t sa = smem_u32(smc);

    const int z = blockIdx.z;
    const int h = z >> 4, b = z & 15;
    const size_t zo = (size_t)z * 262144;

    const __half* Ab = g_Pf + zo + (size_t)(blockIdx.y * 128) * 512;
    const __half* Bb = g_VT + zo + (size_t)(blockIdx.x * 64) * 512;
    float* C = out + (size_t)b * 512 * 4096 + h * 512;

    const int tid = threadIdx.x;
    const int wid = tid >> 5;
    const int lid = tid & 31;
    const int wr  = wid >> 1;
    const int wc  = wid & 1;
    const int g   = lid >> 2;
    const int tg  = lid & 3;

    auto load_stage = [&](int buf, int kb) {
        const uint32_t dbase = sa + buf * PV_STAGE;
        const int kc = kb * 64;
#pragma unroll
        for (int i = 0; i < 4; ++i) {               // P: 1024 chunks
            const int t = tid + (i << 8);
            const int row = t >> 3, c = t & 7;
            cp16(dbase + row * 128 + ((c ^ (row & 7)) << 4),
                 Ab + (size_t)row * 512 + kc + c * 8);
        }
        {                                            // V: 512 chunks
            const int t = tid;
            const int row = t >> 3, c = t & 7;
            cp16(dbase + 16384 + row * 128 + ((c ^ (row & 7)) << 4),
                 Bb + (size_t)row * 512 + kc + c * 8);
        }
        {
            const int t = tid + 256;
            const int row = t >> 3, c = t & 7;
            cp16(dbase + 16384 + row * 128 + ((c ^ (row & 7)) << 4),
                 Bb + (size_t)row * 512 + kc + c * 8);
        }
    };

    float acc[2][4][4];
#pragma unroll
    for (int mt = 0; mt < 2; ++mt)
#pragma unroll
        for (int nt = 0; nt < 4; ++nt)
#pragma unroll
            for (int i = 0; i < 4; ++i) acc[mt][nt][i] = 0.0f;

    const uint32_t sx = (uint32_t)(lid & 7) << 4;
    const uint32_t hb = (uint32_t)(lid >> 4) << 4;
    uint32_t ra[2], rb[2];
#pragma unroll
    for (int mt = 0; mt < 2; ++mt)
        ra[mt] = (uint32_t)(wr * 32 + mt * 16 + (lid & 15)) * 128;
#pragma unroll
    for (int n2 = 0; n2 < 2; ++n2)
        rb[n2] = 16384u + (uint32_t)(wc * 32 + n2 * 16 + (lid & 15)) * 128;

    load_stage(0, 0); CP_COMMIT();
    load_stage(1, 1); CP_COMMIT();

#pragma unroll 1
    for (int kb = 0; kb < 8; ++kb) {
        CP_WAIT1();
        __syncthreads();
        if (kb + 2 < 8) load_stage((kb + 2) % 3, kb + 2);
        CP_COMMIT();

        const uint32_t sbase = sa + (kb % 3) * PV_STAGE;

#pragma unroll
        for (int ks = 0; ks < 4; ++ks) {
            const uint32_t cv = (uint32_t)(ks << 5) + hb;

            uint32_t ah[2][4], bb[4][2];
#pragma unroll
            for (int mt = 0; mt < 2; ++mt)
                ldsm4(ah[mt], sbase + ra[mt] + (cv ^ sx));
#pragma unroll
            for (int n2 = 0; n2 < 2; ++n2) {
                uint32_t r[4];
                ldsm4(r, sbase + rb[n2] + (cv ^ sx));
                bb[n2 * 2][0] = r[0]; bb[n2 * 2][1] = r[2];
                bb[n2 * 2 + 1][0] = r[1]; bb[n2 * 2 + 1][1] = r[3];
            }
#pragma unroll
            for (int mt = 0; mt < 2; ++mt)
#pragma unroll
                for (int nt = 0; nt < 4; ++nt) mma16f(acc[mt][nt], ah[mt], bb[nt]);
        }
    }

    const int rbase = blockIdx.y * 128 + wr * 32 + g;
    const int cbase = blockIdx.x * 64 + wc * 32 + tg * 2;
#pragma unroll
    for (int mt = 0; mt < 2; ++mt) {
#pragma unroll
        for (int nt = 0; nt < 4; ++nt) {
            const int r = rbase + mt * 16;
            const int c = cbase + nt * 8;
            *reinterpret_cast<float2*>(&C[(size_t)r * 4096 + c]) =
                make_float2(acc[mt][nt][0], acc[mt][nt][1]);
            *reinterpret_cast<float2*>(&C[(size_t)(r + 8) * 4096 + c]) =
                make_float2(acc[mt][nt][2], acc[mt][nt][3]);
        }
    }
}

// ===========================================================================
// Splits / transposes
// ===========================================================================
__global__ void split_x(const float* __restrict__ x)
{
    const size_t i = ((size_t)blockIdx.x * 256 + threadIdx.x) * 4;
    const float4 v = *reinterpret_cast<const float4*>(x + i);
    uint32_t h0, l0, h1, l1;
    pack2(v.x, v.y, h0, l0);
    pack2(v.z, v.w, h1, l1);
    *reinterpret_cast<uint2*>(g_xh + i) = make_uint2(h0, h1);
    *reinterpret_cast<uint2*>(g_xl + i) = make_uint2(l0, l1);
    __half2 a = __floats2half2_rn(v.x, v.y);
    __half2 b = __floats2half2_rn(v.z, v.w);
    *reinterpret_cast<__half2*>(g_x16 + i)     = a;
    *reinterpret_cast<__half2*>(g_x16 + i + 2) = b;
}

__global__ void wt_kernel(const float* __restrict__ wq,
                          const float* __restrict__ wk)
{
    __shared__ float t[32][33];
    const int z = blockIdx.z;                 // 0:wq 1:wk
    const float* W = (z == 0) ? wq : wk;      // [512, 4096]
    __nv_bfloat16* WTh = g_WTh + (size_t)z * 4096 * 512;
    __nv_bfloat16* WTl = g_WTl + (size_t)z * 4096 * 512;
    const int n0 = blockIdx.x * 32, k0 = blockIdx.y * 32;
    const int tx = threadIdx.x, ty = threadIdx.y;
#pragma unroll
    for (int i = 0; i < 4; ++i)
        t[ty + i * 8][tx] = W[(size_t)(k0 + ty + i * 8) * 4096 + n0 + tx];
    __syncthreads();
#pragma unroll
    for (int i = 0; i < 4; ++i) {
        const float v = t[tx][ty + i * 8];
        const __nv_bfloat16 hbf = __float2bfloat16_rn(v);
        const float lo = v - __bfloat162float(hbf);
        const size_t idx = (size_t)(n0 + ty + i * 8) * 512 + k0 + tx;
        WTh[idx] = hbf;
        WTl[idx] = __float2bfloat16_rn(lo);
    }
}

__global__ void wt_v(const float* __restrict__ wv)
{
    __shared__ float t[32][33];
    const int n0 = blockIdx.x * 32, k0 = blockIdx.y * 32;
    const int tx = threadIdx.x, ty = threadIdx.y;
#pragma unroll
    for (int i = 0; i < 4; ++i)
        t[ty + i * 8][tx] = wv[(size_t)(k0 + ty + i * 8) * 4096 + n0 + tx];
    __syncthreads();
#pragma unroll
    for (int i = 0; i < 4; ++i) {
        const float v = t[tx][ty + i * 8];
        const __half hf = __float2half_rn(v);
        const float lo = v - __half2float(hf);
        const size_t idx = (size_t)(n0 + ty + i * 8) * 512 + k0 + tx;
        g_WVh[idx] = hf;
        g_WVl[idx] = __float2half_rn(lo);
    }
}

__global__ void vt_kernel()
{
    __shared__ float t[32][33];
    const int z = blockIdx.z;                 // h*16 + b
    const int h = z >> 4, b = z & 15;
    const int j0 = blockIdx.x * 32, d0 = blockIdx.y * 32;
    const int tx = threadIdx.x, ty = threadIdx.y;
#pragma unroll
    for (int i = 0; i < 4; ++i)
        t[ty + i * 8][tx] = g_V[(size_t)(b * 512 + j0 + ty + i * 8) * 4096 + h * 512 + d0 + tx];
    __syncthreads();
    __half* VT = g_VT + (size_t)z * 512 * 512;
#pragma unroll
    for (int i = 0; i < 4; ++i) {
        const float v = t[tx][ty + i * 8];
        VT[(size_t)(d0 + ty + i * 8) * 512 + j0 + tx] = __float2half_rn(v);
    }
}

// ===========================================================================
// Softmax over rows of g_P (512 wide), writes single fp16 plane g_Pf.
// ===========================================================================
__global__ void softmax_kernel()
{
    const size_t row = blockIdx.x;
    const float* p = g_P + row * 512;
    const int t = threadIdx.x;

    float2 v = reinterpret_cast<const float2*>(p)[t];
    __shared__ float red[8];

    float m = fmaxf(v.x, v.y);
#pragma unroll
    for (int o = 16; o > 0; o >>= 1) m = fmaxf(m, __shfl_xor_sync(0xFFFFFFFFu, m, o));
    if ((t & 31) == 0) red[t >> 5] = m;
    __syncthreads();
    m = red[0];
#pragma unroll
    for (int i = 1; i < 8; i++) m = fmaxf(m, red[i]);
    __syncthreads();

    const float e0 = __expf(v.x - m);
    const float e1 = __expf(v.y - m);

    float s = e0 + e1;
#pragma unroll
    for (int o = 16; o > 0; o >>= 1) s += __shfl_xor_sync(0xFFFFFFFFu, s, o);
    if ((t & 31) == 0) red[t >> 5] = s;
    __syncthreads();
    s = red[0];
#pragma unroll
    for (int i = 1; i < 8; i++) s += red[i];

    const float inv = 1.0f / s;
    reinterpret_cast<__half2*>(g_Pf + row * 512)[t] =
        __floats2half2_rn(e0 * inv, e1 * inv);
}

// ===========================================================================
// Launch
// ===========================================================================
extern "C" void kernel_launch(void* const* d_in, const int* in_sizes, int n_in,
                              void* d_out, int out_size)
{
    const float* x  = (const float*)d_in[0];
    const float* wq = (const float*)d_in[1];
    const float* wk = (const float*)d_in[2];
    const float* wv = (const float*)d_in[3];
    float* out = (float*)d_out;

    cudaFuncSetAttribute(proj_mm, cudaFuncAttributeMaxDynamicSharedMemorySize, GEMM_SMEM);
    cudaFuncSetAttribute(proj_v,  cudaFuncAttributeMaxDynamicSharedMemorySize, PJV_SMEM);
    cudaFuncSetAttribute(qk_mm,   cudaFuncAttributeMaxDynamicSharedMemorySize, GEMM_SMEM);
    cudaFuncSetAttribute(pv_mm,   cudaFuncAttributeMaxDynamicSharedMemorySize, PV_SMEM);

    split_x<<<4096, 256>>>(x);                                   // 1
    wt_kernel<<<dim3(128, 16, 2), dim3(32, 8)>>>(wq, wk);        // 2
    wt_v<<<dim3(128, 16), dim3(32, 8)>>>(wv);                    // 3
    proj_mm<<<dim3(64, 64, 2), 256, GEMM_SMEM>>>();              // 4 <- profiled
    proj_v<<<dim3(64, 64), 256, PJV_SMEM>>>();                   // 5
    qk_mm<<<dim3(8, 4, 128), 256, GEMM_SMEM>>>();                // 6
    softmax_kernel<<<65536, 256>>>();                            // 7
    vt_kernel<<<dim3(16, 16, 128), dim3(32, 8)>>>();             // 8
    pv_mm<<<dim3(8, 4, 128), 256, PV_SMEM>>>(out);               // 9
}

// round 13
// speedup vs baseline: 3.3942x; 1.0958x over previous
#include <cuda_runtime.h>
#include <cuda_bf16.h>
#include <cuda_fp16.h>
#include <cstdint>

// ---------------------------------------------------------------------------
// Problem: B=16, S=512, F=512, H=8, D=512.
// Logit path (Q,K proj; qk): bf16 hi/lo 3-term emulation (unchanged).
// V path: single-pass fp16 proj (wv16 x x16) with fused transpose epilogue
//         writing VT fp16 directly; PV = 1 fp16 pass.
// ---------------------------------------------------------------------------
__device__ float g_P[128 * 512 * 512];      // scores fp32 (softmax input)

__device__ __nv_bfloat16 g_xh[8192 * 512],      g_xl[8192 * 512];
__device__ __nv_bfloat16 g_WTh[2 * 4096 * 512], g_WTl[2 * 4096 * 512]; // wq,wk
__device__ __nv_bfloat16 g_Qh[8192 * 4096],     g_Ql[8192 * 4096];
__device__ __nv_bfloat16 g_Kh[8192 * 4096],     g_Kl[8192 * 4096];

__device__ __half g_x16[8192 * 512];        // x, single fp16 plane
__device__ __half g_WV16[4096 * 512];       // wv^T, single fp16 plane
__device__ __half g_VT[128 * 512 * 512];    // V^T per (h,b): [z][d][j], fp16
__device__ __half g_Pf[128 * 512 * 512];    // softmax probs fp16

// ===========================================================================
// Helpers
// ===========================================================================
__device__ __forceinline__ uint32_t smem_u32(const void* p) {
    uint32_t a;
    asm("{ .reg .u64 t; cvta.to.shared.u64 t, %1; cvt.u32.u64 %0, t; }"
        : "=r"(a) : "l"(p));
    return a;
}

__device__ __forceinline__ void cp16(uint32_t dst, const void* src) {
    asm volatile("cp.async.cg.shared.global [%0], [%1], 16;"
                 :: "r"(dst), "l"(src) : "memory");
}
#define CP_COMMIT() asm volatile("cp.async.commit_group;" ::: "memory")
#define CP_WAIT1()  asm volatile("cp.async.wait_group 1;" ::: "memory")

// pack two fp32 into bf16x2 hi-plane word + lo-plane word (rn rounding)
__device__ __forceinline__ void pack2(float x0, float x1, uint32_t& h, uint32_t& l) {
    asm("cvt.rn.bf16x2.f32 %0, %1, %2;" : "=r"(h) : "f"(x1), "f"(x0));
    float f0 = __uint_as_float(h << 16);
    float f1 = __uint_as_float(h & 0xFFFF0000u);
    float l0 = x0 - f0, l1 = x1 - f1;
    asm("cvt.rn.bf16x2.f32 %0, %1, %2;" : "=r"(l) : "f"(l1), "f"(l0));
}

// D += A * B : m16n8k16 bf16, row.col, fp32 accumulate
__device__ __forceinline__ void mma16(float* c, const uint32_t* a, const uint32_t* b) {
    asm volatile(
        "mma.sync.aligned.m16n8k16.row.col.f32.bf16.bf16.f32 "
        "{%0,%1,%2,%3}, {%4,%5,%6,%7}, {%8,%9}, {%0,%1,%2,%3};"
        : "+f"(c[0]), "+f"(c[1]), "+f"(c[2]), "+f"(c[3])
        : "r"(a[0]), "r"(a[1]), "r"(a[2]), "r"(a[3]), "r"(b[0]), "r"(b[1]));
}

// D += A * B : m16n8k16 fp16, row.col, fp32 accumulate
__device__ __forceinline__ void mma16f(float* c, const uint32_t* a, const uint32_t* b) {
    asm volatile(
        "mma.sync.aligned.m16n8k16.row.col.f32.f16.f16.f32 "
        "{%0,%1,%2,%3}, {%4,%5,%6,%7}, {%8,%9}, {%0,%1,%2,%3};"
        : "+f"(c[0]), "+f"(c[1]), "+f"(c[2]), "+f"(c[3])
        : "r"(a[0]), "r"(a[1]), "r"(a[2]), "r"(a[3]), "r"(b[0]), "r"(b[1]));
}

__device__ __forceinline__ void ldsm4(uint32_t* r, uint32_t addr) {
    asm volatile("ldmatrix.sync.aligned.m8n8.x4.shared.b16 {%0,%1,%2,%3}, [%4];"
                 : "=r"(r[0]), "=r"(r[1]), "=r"(r[2]), "=r"(r[3]) : "r"(addr));
}

// ===========================================================================
// NT GEMM on bf16 hi/lo planes (3-term emulation), 256 threads. [R10 core]
//   C[128x64] tile, 8 warps 4(M)x2(N), warp tile 32x32, 3 CTAs/SM.
// ===========================================================================
#define KB        32
#define NKB       16
#define STAGE     24576
#define GEMM_SMEM (3 * STAGE)   // 73728

template <int EPI>   // 0: fp32 C ; 1: bf16 hi/lo planes
__device__ __forceinline__ void gemm_nt_bf16(
    const __nv_bfloat16* __restrict__ Ah, const __nv_bfloat16* __restrict__ Al, int lda,
    const __nv_bfloat16* __restrict__ Bh, const __nv_bfloat16* __restrict__ Bl, int ldb,
    float* __restrict__ C, __nv_bfloat16* __restrict__ Ch,
    __nv_bfloat16* __restrict__ Cl, int ldc)
{
    extern __shared__ __align__(128) char smc[];
    const uint32_t sa = smem_u32(smc);

    const int tid = threadIdx.x;
    const int wid = tid >> 5;
    const int lid = tid & 31;
    const int wr  = wid >> 1;          // 0..3 (M)
    const int wc  = wid & 1;           // 0..1 (N)
    const int g   = lid >> 2;
    const int tg  = lid & 3;

    const __nv_bfloat16* Abh = Ah + (size_t)(blockIdx.y * 128) * lda;
    const __nv_bfloat16* Abl = Al + (size_t)(blockIdx.y * 128) * lda;
    const __nv_bfloat16* Bbh = Bh + (size_t)(blockIdx.x * 64) * ldb;
    const __nv_bfloat16* Bbl = Bl + (size_t)(blockIdx.x * 64) * ldb;

    auto load_stage = [&](int buf, int kb) {
        const uint32_t dbase = sa + buf * STAGE;
        const int kc = kb * KB;
#pragma unroll
        for (int i = 0; i < 4; ++i) {               // A: 1024 chunks
            const int t = tid + (i << 8);
            const int row = t >> 3, c = t & 7;
            const __nv_bfloat16* src =
                ((c & 4) ? Abl : Abh) + (size_t)row * lda + kc + (c & 3) * 8;
            cp16(dbase + row * 128 + ((c ^ (row & 7)) << 4), src);
        }
        {
            const int t = tid + 1024;
            const int row = (t >> 3) & 63, c = t & 7;
            const __nv_bfloat16* src =
                ((c & 4) ? Bbl : Bbh) + (size_t)row * ldb + kc + (c & 3) * 8;
            cp16(dbase + 16384 + row * 128 + ((c ^ (row & 7)) << 4), src);
        }
        {
            const int t = tid + 1280;
            const int row = (t >> 3) & 63, c = t & 7;
            const __nv_bfloat16* src =
                ((c & 4) ? Bbl : Bbh) + (size_t)row * ldb + kc + (c & 3) * 8;
            cp16(dbase + 16384 + row * 128 + ((c ^ (row & 7)) << 4), src);
        }
    };

    float acc[2][4][4];
#pragma unroll
    for (int mt = 0; mt < 2; ++mt)
#pragma unroll
        for (int nt = 0; nt < 4; ++nt)
#pragma unroll
            for (int i = 0; i < 4; ++i) acc[mt][nt][i] = 0.0f;

    const uint32_t sx = (uint32_t)(lid & 7) << 4;
    const uint32_t hb = (uint32_t)(lid >> 4) << 4;
    uint32_t ra[2], rb[2];
#pragma unroll
    for (int mt = 0; mt < 2; ++mt)
        ra[mt] = (uint32_t)(wr * 32 + mt * 16 + (lid & 15)) * 128;
#pragma unroll
    for (int n2 = 0; n2 < 2; ++n2)
        rb[n2] = 16384u + (uint32_t)(wc * 32 + n2 * 16 + (lid & 15)) * 128;

    load_stage(0, 0); CP_COMMIT();
    load_stage(1, 1); CP_COMMIT();

#pragma unroll 1
    for (int kb = 0; kb < NKB; ++kb) {
        CP_WAIT1();
        __syncthreads();
        if (kb + 2 < NKB) load_stage((kb + 2) % 3, kb + 2);
        CP_COMMIT();

        const uint32_t sbase = sa + (kb % 3) * STAGE;

#pragma unroll
        for (int ks = 0; ks < 2; ++ks) {
            const uint32_t cvh = (uint32_t)(ks << 5) + hb;
            const uint32_t cvl = cvh + 64;

            uint32_t ah[2][4], al[2][4], bb[4][2];
#pragma unroll
            for (int mt = 0; mt < 2; ++mt) {
                ldsm4(ah[mt], sbase + ra[mt] + (cvh ^ sx));
                ldsm4(al[mt], sbase + ra[mt] + (cvl ^ sx));
            }
#pragma unroll
            for (int n2 = 0; n2 < 2; ++n2) {
                uint32_t r[4];
                ldsm4(r, sbase + rb[n2] + (cvh ^ sx));
                bb[n2 * 2][0] = r[0]; bb[n2 * 2][1] = r[2];
                bb[n2 * 2 + 1][0] = r[1]; bb[n2 * 2 + 1][1] = r[3];
            }
#pragma unroll
            for (int mt = 0; mt < 2; ++mt)
#pragma unroll
                for (int nt = 0; nt < 4; ++nt) mma16(acc[mt][nt], ah[mt], bb[nt]);
#pragma unroll
            for (int mt = 0; mt < 2; ++mt)
#pragma unroll
                for (int nt = 0; nt < 4; ++nt) mma16(acc[mt][nt], al[mt], bb[nt]);
#pragma unroll
            for (int n2 = 0; n2 < 2; ++n2) {
                uint32_t r[4];
                ldsm4(r, sbase + rb[n2] + (cvl ^ sx));
                bb[n2 * 2][0] = r[0]; bb[n2 * 2][1] = r[2];
                bb[n2 * 2 + 1][0] = r[1]; bb[n2 * 2 + 1][1] = r[3];
            }
#pragma unroll
            for (int mt = 0; mt < 2; ++mt)
#pragma unroll
                for (int nt = 0; nt < 4; ++nt) mma16(acc[mt][nt], ah[mt], bb[nt]);
        }
    }

    const int rbase = blockIdx.y * 128 + wr * 32 + g;
    const int cbase = blockIdx.x * 64 + wc * 32 + tg * 2;
#pragma unroll
    for (int mt = 0; mt < 2; ++mt) {
#pragma unroll
        for (int nt = 0; nt < 4; ++nt) {
            const int r = rbase + mt * 16;
            const int c = cbase + nt * 8;
            if (EPI == 0) {
                *reinterpret_cast<float2*>(&C[(size_t)r * ldc + c]) =
                    make_float2(acc[mt][nt][0], acc[mt][nt][1]);
                *reinterpret_cast<float2*>(&C[(size_t)(r + 8) * ldc + c]) =
                    make_float2(acc[mt][nt][2], acc[mt][nt][3]);
            } else {
                uint32_t h, l;
                pack2(acc[mt][nt][0], acc[mt][nt][1], h, l);
                *reinterpret_cast<uint32_t*>(Ch + (size_t)r * ldc + c) = h;
                *reinterpret_cast<uint32_t*>(Cl + (size_t)r * ldc + c) = l;
                pack2(acc[mt][nt][2], acc[mt][nt][3], h, l);
                *reinterpret_cast<uint32_t*>(Ch + (size_t)(r + 8) * ldc + c) = h;
                *reinterpret_cast<uint32_t*>(Cl + (size_t)(r + 8) * ldc + c) = l;
            }
        }
    }
}

// ===========================================================================
// Q,K projections (bf16 3-term)
// ===========================================================================
__global__ void __launch_bounds__(256, 3)
proj_mm()
{
    const int z = blockIdx.z;                 // 0:Q 1:K
    const __nv_bfloat16* Bh = g_WTh + (size_t)z * 4096 * 512;
    const __nv_bfloat16* Bl = g_WTl + (size_t)z * 4096 * 512;
    if (z == 0)
        gemm_nt_bf16<1>(g_xh, g_xl, 512, Bh, Bl, 512, nullptr, g_Qh, g_Ql, 4096);
    else
        gemm_nt_bf16<1>(g_xh, g_xl, 512, Bh, Bl, 512, nullptr, g_Kh, g_Kl, 4096);
}

__global__ void __launch_bounds__(256, 3)
qk_mm()
{
    const int z = blockIdx.z;                 // h*16 + b
    const int h = z >> 4, b = z & 15;
    const size_t off = (size_t)b * 512 * 4096 + h * 512;
    gemm_nt_bf16<0>(g_Qh + off, g_Ql + off, 4096,
                    g_Kh + off, g_Kl + off, 4096,
                    g_P + (size_t)z * 512 * 512, nullptr, nullptr, 512);
}

// ===========================================================================
// V projection, single fp16 pass with FUSED TRANSPOSE epilogue.
//   A = wv^T [4096 dcols, 512 k] fp16 ; B = x [8192 tokens, 512 k] fp16.
//   C tile [128 dcols x 64 tokens] -> written directly as VT[z][d][j] fp16.
//   z = h*16 + b, h = blockIdx.y>>2 (128 d per CTA), b = blockIdx.x>>3.
// KB=64, stage 24KB (A 128 rows @0, B 64 rows @16K), 3 stages, 3 CTAs/SM.
// ===========================================================================
#define PV_STAGE 24576
#define PV_SMEM  (3 * PV_STAGE)   // 73728

__global__ void __launch_bounds__(256, 3)
proj_v()
{
    extern __shared__ __align__(128) char smc[];
    const uint32_t sa = smem_u32(smc);

    const __half* Ab = g_WV16 + (size_t)(blockIdx.y * 128) * 512;
    const __half* Bb = g_x16  + (size_t)(blockIdx.x * 64) * 512;

    const int tid = threadIdx.x;
    const int wid = tid >> 5;
    const int lid = tid & 31;
    const int wr  = wid >> 1;
    const int wc  = wid & 1;
    const int g   = lid >> 2;
    const int tg  = lid & 3;

    auto load_stage = [&](int buf, int kb) {
        const uint32_t dbase = sa + buf * PV_STAGE;
        const int kc = kb * 64;
#pragma unroll
        for (int i = 0; i < 4; ++i) {               // A: 1024 chunks
            const int t = tid + (i << 8);
            const int row = t >> 3, c = t & 7;
            cp16(dbase + row * 128 + ((c ^ (row & 7)) << 4),
                 Ab + (size_t)row * 512 + kc + c * 8);
        }
        {                                            // B: 512 chunks
            const int t = tid;
            const int row = t >> 3, c = t & 7;
            cp16(dbase + 16384 + row * 128 + ((c ^ (row & 7)) << 4),
                 Bb + (size_t)row * 512 + kc + c * 8);
        }
        {
            const int t = tid + 256;
            const int row = t >> 3, c = t & 7;
            cp16(dbase + 16384 + row * 128 + ((c ^ (row & 7)) << 4),
                 Bb + (size_t)row * 512 + kc + c * 8);
        }
    };

    float acc[2][4][4];
#pragma unroll
    for (int mt = 0; mt < 2; ++mt)
#pragma unroll
        for (int nt = 0; nt < 4; ++nt)
#pragma unroll
            for (int i = 0; i < 4; ++i) acc[mt][nt][i] = 0.0f;

    const uint32_t sx = (uint32_t)(lid & 7) << 4;
    const uint32_t hb = (uint32_t)(lid >> 4) << 4;
    uint32_t ra[2], rb[2];
#pragma unroll
    for (int mt = 0; mt < 2; ++mt)
        ra[mt] = (uint32_t)(wr * 32 + mt * 16 + (lid & 15)) * 128;
#pragma unroll
    for (int n2 = 0; n2 < 2; ++n2)
        rb[n2] = 16384u + (uint32_t)(wc * 32 + n2 * 16 + (lid & 15)) * 128;

    load_stage(0, 0); CP_COMMIT();
    load_stage(1, 1); CP_COMMIT();

#pragma unroll 1
    for (int kb = 0; kb < 8; ++kb) {
        CP_WAIT1();
        __syncthreads();
        if (kb + 2 < 8) load_stage((kb + 2) % 3, kb + 2);
        CP_COMMIT();

        const uint32_t sbase = sa + (kb % 3) * PV_STAGE;

#pragma unroll
        for (int ks = 0; ks < 4; ++ks) {
            const uint32_t cv = (uint32_t)(ks << 5) + hb;

            uint32_t ah[2][4], bb[4][2];
#pragma unroll
            for (int mt = 0; mt < 2; ++mt)
                ldsm4(ah[mt], sbase + ra[mt] + (cv ^ sx));
#pragma unroll
            for (int n2 = 0; n2 < 2; ++n2) {
                uint32_t r[4];
                ldsm4(r, sbase + rb[n2] + (cv ^ sx));
                bb[n2 * 2][0] = r[0]; bb[n2 * 2][1] = r[2];
                bb[n2 * 2 + 1][0] = r[1]; bb[n2 * 2 + 1][1] = r[3];
            }
#pragma unroll
            for (int mt = 0; mt < 2; ++mt)
#pragma unroll
                for (int nt = 0; nt < 4; ++nt) mma16f(acc[mt][nt], ah[mt], bb[nt]);
        }
    }

    // ---- fused transpose epilogue: C[d, token] -> VT[z][d][j] fp16 ----
    const int hH = blockIdx.y >> 2;            // head
    const int bB = blockIdx.x >> 3;            // batch
    __half* VT = g_VT + (size_t)(hH * 16 + bB) * 262144;
    const int rloc = (blockIdx.y & 3) * 128 + wr * 32 + g;   // d within head
    const int cloc = (blockIdx.x & 7) * 64 + wc * 32 + tg * 2; // j within batch
#pragma unroll
    for (int mt = 0; mt < 2; ++mt) {
#pragma unroll
        for (int nt = 0; nt < 4; ++nt) {
            const int r = rloc + mt * 16;
            const int c = cloc + nt * 8;
            __half2 v0 = __floats2half2_rn(acc[mt][nt][0], acc[mt][nt][1]);
            __half2 v1 = __floats2half2_rn(acc[mt][nt][2], acc[mt][nt][3]);
            *reinterpret_cast<__half2*>(VT + (size_t)r * 512 + c)       = v0;
            *reinterpret_cast<__half2*>(VT + (size_t)(r + 8) * 512 + c) = v1;
        }
    }
}

// ===========================================================================
// PV GEMM: single fp16 P x single fp16 V, 1 MMA pass. C[128x64] fp32.
// ===========================================================================
__global__ void __launch_bounds__(256, 3)
pv_mm(float* __restrict__ out)
{
    extern __shared__ __align__(128) char smc[];
    const uint32_t sa = smem_u32(smc);

    const int z = blockIdx.z;
    const int h = z >> 4, b = z & 15;
    const size_t zo = (size_t)z * 262144;

    const __half* Ab = g_Pf + zo + (size_t)(blockIdx.y * 128) * 512;
    const __half* Bb = g_VT + zo + (size_t)(blockIdx.x * 64) * 512;
    float* C = out + (size_t)b * 512 * 4096 + h * 512;

    const int tid = threadIdx.x;
    const int wid = tid >> 5;
    const int lid = tid & 31;
    const int wr  = wid >> 1;
    const int wc  = wid & 1;
    const int g   = lid >> 2;
    const int tg  = lid & 3;

    auto load_stage = [&](int buf, int kb) {
        const uint32_t dbase = sa + buf * PV_STAGE;
        const int kc = kb * 64;
#pragma unroll
        for (int i = 0; i < 4; ++i) {
            const int t = tid + (i << 8);
            const int row = t >> 3, c = t & 7;
            cp16(dbase + row * 128 + ((c ^ (row & 7)) << 4),
                 Ab + (size_t)row * 512 + kc + c * 8);
        }
        {
            const int t = tid;
            const int row = t >> 3, c = t & 7;
            cp16(dbase + 16384 + row * 128 + ((c ^ (row & 7)) << 4),
                 Bb + (size_t)row * 512 + kc + c * 8);
        }
        {
            const int t = tid + 256;
            const int row = t >> 3, c = t & 7;
            cp16(dbase + 16384 + row * 128 + ((c ^ (row & 7)) << 4),
                 Bb + (size_t)row * 512 + kc + c * 8);
        }
    };

    float acc[2][4][4];
#pragma unroll
    for (int mt = 0; mt < 2; ++mt)
#pragma unroll
        for (int nt = 0; nt < 4; ++nt)
#pragma unroll
            for (int i = 0; i < 4; ++i) acc[mt][nt][i] = 0.0f;

    const uint32_t sx = (uint32_t)(lid & 7) << 4;
    const uint32_t hb = (uint32_t)(lid >> 4) << 4;
    uint32_t ra[2], rb[2];
#pragma unroll
    for (int mt = 0; mt < 2; ++mt)
        ra[mt] = (uint32_t)(wr * 32 + mt * 16 + (lid & 15)) * 128;
#pragma unroll
    for (int n2 = 0; n2 < 2; ++n2)
        rb[n2] = 16384u + (uint32_t)(wc * 32 + n2 * 16 + (lid & 15)) * 128;

    load_stage(0, 0); CP_COMMIT();
    load_stage(1, 1); CP_COMMIT();

#pragma unroll 1
    for (int kb = 0; kb < 8; ++kb) {
        CP_WAIT1();
        __syncthreads();
        if (kb + 2 < 8) load_stage((kb + 2) % 3, kb + 2);
        CP_COMMIT();

        const uint32_t sbase = sa + (kb % 3) * PV_STAGE;

#pragma unroll
        for (int ks = 0; ks < 4; ++ks) {
            const uint32_t cv = (uint32_t)(ks << 5) + hb;

            uint32_t ah[2][4], bb[4][2];
#pragma unroll
            for (int mt = 0; mt < 2; ++mt)
                ldsm4(ah[mt], sbase + ra[mt] + (cv ^ sx));
#pragma unroll
            for (int n2 = 0; n2 < 2; ++n2) {
                uint32_t r[4];
                ldsm4(r, sbase + rb[n2] + (cv ^ sx));
                bb[n2 * 2][0] = r[0]; bb[n2 * 2][1] = r[2];
                bb[n2 * 2 + 1][0] = r[1]; bb[n2 * 2 + 1][1] = r[3];
            }
#pragma unroll
            for (int mt = 0; mt < 2; ++mt)
#pragma unroll
                for (int nt = 0; nt < 4; ++nt) mma16f(acc[mt][nt], ah[mt], bb[nt]);
        }
    }

    const int rbase = blockIdx.y * 128 + wr * 32 + g;
    const int cbase = blockIdx.x * 64 + wc * 32 + tg * 2;
#pragma unroll
    for (int mt = 0; mt < 2; ++mt) {
#pragma unroll
        for (int nt = 0; nt < 4; ++nt) {
            const int r = rbase + mt * 16;
            const int c = cbase + nt * 8;
            *reinterpret_cast<float2*>(&C[(size_t)r * 4096 + c]) =
                make_float2(acc[mt][nt][0], acc[mt][nt][1]);
            *reinterpret_cast<float2*>(&C[(size_t)(r + 8) * 4096 + c]) =
                make_float2(acc[mt][nt][2], acc[mt][nt][3]);
        }
    }
}

// ===========================================================================
// Splits / transposes
// ===========================================================================
__global__ void split_x(const float* __restrict__ x)
{
    const size_t i = ((size_t)blockIdx.x * 256 + threadIdx.x) * 4;
    const float4 v = *reinterpret_cast<const float4*>(x + i);
    uint32_t h0, l0, h1, l1;
    pack2(v.x, v.y, h0, l0);
    pack2(v.z, v.w, h1, l1);
    *reinterpret_cast<uint2*>(g_xh + i) = make_uint2(h0, h1);
    *reinterpret_cast<uint2*>(g_xl + i) = make_uint2(l0, l1);
    __half2 a = __floats2half2_rn(v.x, v.y);
    __half2 b = __floats2half2_rn(v.z, v.w);
    *reinterpret_cast<__half2*>(g_x16 + i)     = a;
    *reinterpret_cast<__half2*>(g_x16 + i + 2) = b;
}

__global__ void wt_kernel(const float* __restrict__ wq,
                          const float* __restrict__ wk)
{
    __shared__ float t[32][33];
    const int z = blockIdx.z;                 // 0:wq 1:wk
    const float* W = (z == 0) ? wq : wk;      // [512, 4096]
    __nv_bfloat16* WTh = g_WTh + (size_t)z * 4096 * 512;
    __nv_bfloat16* WTl = g_WTl + (size_t)z * 4096 * 512;
    const int n0 = blockIdx.x * 32, k0 = blockIdx.y * 32;
    const int tx = threadIdx.x, ty = threadIdx.y;
#pragma unroll
    for (int i = 0; i < 4; ++i)
        t[ty + i * 8][tx] = W[(size_t)(k0 + ty + i * 8) * 4096 + n0 + tx];
    __syncthreads();
#pragma unroll
    for (int i = 0; i < 4; ++i) {
        const float v = t[tx][ty + i * 8];
        const __nv_bfloat16 hbf = __float2bfloat16_rn(v);
        const float lo = v - __bfloat162float(hbf);
        const size_t idx = (size_t)(n0 + ty + i * 8) * 512 + k0 + tx;
        WTh[idx] = hbf;
        WTl[idx] = __float2bfloat16_rn(lo);
    }
}

__global__ void wt_v(const float* __restrict__ wv)
{
    __shared__ float t[32][33];
    const int n0 = blockIdx.x * 32, k0 = blockIdx.y * 32;
    const int tx = threadIdx.x, ty = threadIdx.y;
#pragma unroll
    for (int i = 0; i < 4; ++i)
        t[ty + i * 8][tx] = wv[(size_t)(k0 + ty + i * 8) * 4096 + n0 + tx];
    __syncthreads();
#pragma unroll
    for (int i = 0; i < 4; ++i) {
        const float v = t[tx][ty + i * 8];
        g_WV16[(size_t)(n0 + ty + i * 8) * 512 + k0 + tx] = __float2half_rn(v);
    }
}

// ===========================================================================
// Softmax over rows of g_P (512 wide), writes single fp16 plane g_Pf.
// ===========================================================================
__global__ void softmax_kernel()
{
    const size_t row = blockIdx.x;
    const float* p = g_P + row * 512;
    const int t = threadIdx.x;

    float2 v = reinterpret_cast<const float2*>(p)[t];
    __shared__ float red[8];

    float m = fmaxf(v.x, v.y);
#pragma unroll
    for (int o = 16; o > 0; o >>= 1) m = fmaxf(m, __shfl_xor_sync(0xFFFFFFFFu, m, o));
    if ((t & 31) == 0) red[t >> 5] = m;
    __syncthreads();
    m = red[0];
#pragma unroll
    for (int i = 1; i < 8; i++) m = fmaxf(m, red[i]);
    __syncthreads();

    const float e0 = __expf(v.x - m);
    const float e1 = __expf(v.y - m);

    float s = e0 + e1;
#pragma unroll
    for (int o = 16; o > 0; o >>= 1) s += __shfl_xor_sync(0xFFFFFFFFu, s, o);
    if ((t & 31) == 0) red[t >> 5] = s;
    __syncthreads();
    s = red[0];
#pragma unroll
    for (int i = 1; i < 8; i++) s += red[i];

    const float inv = 1.0f / s;
    reinterpret_cast<__half2*>(g_Pf + row * 512)[t] =
        __floats2half2_rn(e0 * inv, e1 * inv);
}

// ===========================================================================
// Launch
// ===========================================================================
extern "C" void kernel_launch(void* const* d_in, const int* in_sizes, int n_in,
                              void* d_out, int out_size)
{
    const float* x  = (const float*)d_in[0];
    const float* wq = (const float*)d_in[1];
    const float* wk = (const float*)d_in[2];
    const float* wv = (const float*)d_in[3];
    float* out = (float*)d_out;

    cudaFuncSetAttribute(proj_mm, cudaFuncAttributeMaxDynamicSharedMemorySize, GEMM_SMEM);
    cudaFuncSetAttribute(proj_v,  cudaFuncAttributeMaxDynamicSharedMemorySize, PV_SMEM);
    cudaFuncSetAttribute(qk_mm,   cudaFuncAttributeMaxDynamicSharedMemorySize, GEMM_SMEM);
    cudaFuncSetAttribute(pv_mm,   cudaFuncAttributeMaxDynamicSharedMemorySize, PV_SMEM);

    split_x<<<4096, 256>>>(x);                                   // 1
    wt_kernel<<<dim3(128, 16, 2), dim3(32, 8)>>>(wq, wk);        // 2
    wt_v<<<dim3(128, 16), dim3(32, 8)>>>(wv);                    // 3
    proj_mm<<<dim3(64, 64, 2), 256, GEMM_SMEM>>>();              // 4 <- profiled
    proj_v<<<dim3(128, 32), 256, PV_SMEM>>>();                   // 5 (VT direct)
    qk_mm<<<dim3(8, 4, 128), 256, GEMM_SMEM>>>();                // 6
    softmax_kernel<<<65536, 256>>>();                            // 7
    pv_mm<<<dim3(8, 4, 128), 256, PV_SMEM>>>(out);               // 8
}

// round 14
// speedup vs baseline: 3.4029x; 1.0026x over previous
#include <cuda_runtime.h>
#include <cuda_bf16.h>
#include <cuda_fp16.h>
#include <cstdint>

// ---------------------------------------------------------------------------
// Problem: B=16, S=512, F=512, H=8, D=512.
// Logit path (Q,K proj; qk): bf16 hi/lo 3-term emulation.
// V path: single-pass fp16 proj (wv16 x x16) with fused transpose epilogue
//         writing VT fp16 directly; PV = 1 fp16 pass.
// R14: proj_v merged into qk launch (tail overlap); wt_v merged into wt.
// ---------------------------------------------------------------------------
__device__ float g_P[128 * 512 * 512];      // scores fp32 (softmax input)

__device__ __nv_bfloat16 g_xh[8192 * 512],      g_xl[8192 * 512];
__device__ __nv_bfloat16 g_WTh[2 * 4096 * 512], g_WTl[2 * 4096 * 512]; // wq,wk
__device__ __nv_bfloat16 g_Qh[8192 * 4096],     g_Ql[8192 * 4096];
__device__ __nv_bfloat16 g_Kh[8192 * 4096],     g_Kl[8192 * 4096];

__device__ __half g_x16[8192 * 512];        // x, single fp16 plane
__device__ __half g_WV16[4096 * 512];       // wv^T, single fp16 plane
__device__ __half g_VT[128 * 512 * 512];    // V^T per (h,b): [z][d][j], fp16
__device__ __half g_Pf[128 * 512 * 512];    // softmax probs fp16

// ===========================================================================
// Helpers
// ===========================================================================
__device__ __forceinline__ uint32_t smem_u32(const void* p) {
    uint32_t a;
    asm("{ .reg .u64 t; cvta.to.shared.u64 t, %1; cvt.u32.u64 %0, t; }"
        : "=r"(a) : "l"(p));
    return a;
}

__device__ __forceinline__ void cp16(uint32_t dst, const void* src) {
    asm volatile("cp.async.cg.shared.global [%0], [%1], 16;"
                 :: "r"(dst), "l"(src) : "memory");
}
#define CP_COMMIT() asm volatile("cp.async.commit_group;" ::: "memory")
#define CP_WAIT1()  asm volatile("cp.async.wait_group 1;" ::: "memory")

// pack two fp32 into bf16x2 hi-plane word + lo-plane word (rn rounding)
__device__ __forceinline__ void pack2(float x0, float x1, uint32_t& h, uint32_t& l) {
    asm("cvt.rn.bf16x2.f32 %0, %1, %2;" : "=r"(h) : "f"(x1), "f"(x0));
    float f0 = __uint_as_float(h << 16);
    float f1 = __uint_as_float(h & 0xFFFF0000u);
    float l0 = x0 - f0, l1 = x1 - f1;
    asm("cvt.rn.bf16x2.f32 %0, %1, %2;" : "=r"(l) : "f"(l1), "f"(l0));
}

// D += A * B : m16n8k16 bf16, row.col, fp32 accumulate
__device__ __forceinline__ void mma16(float* c, const uint32_t* a, const uint32_t* b) {
    asm volatile(
        "mma.sync.aligned.m16n8k16.row.col.f32.bf16.bf16.f32 "
        "{%0,%1,%2,%3}, {%4,%5,%6,%7}, {%8,%9}, {%0,%1,%2,%3};"
        : "+f"(c[0]), "+f"(c[1]), "+f"(c[2]), "+f"(c[3])
        : "r"(a[0]), "r"(a[1]), "r"(a[2]), "r"(a[3]), "r"(b[0]), "r"(b[1]));
}

// D += A * B : m16n8k16 fp16, row.col, fp32 accumulate
__device__ __forceinline__ void mma16f(float* c, const uint32_t* a, const uint32_t* b) {
    asm volatile(
        "mma.sync.aligned.m16n8k16.row.col.f32.f16.f16.f32 "
        "{%0,%1,%2,%3}, {%4,%5,%6,%7}, {%8,%9}, {%0,%1,%2,%3};"
        : "+f"(c[0]), "+f"(c[1]), "+f"(c[2]), "+f"(c[3])
        : "r"(a[0]), "r"(a[1]), "r"(a[2]), "r"(a[3]), "r"(b[0]), "r"(b[1]));
}

__device__ __forceinline__ void ldsm4(uint32_t* r, uint32_t addr) {
    asm volatile("ldmatrix.sync.aligned.m8n8.x4.shared.b16 {%0,%1,%2,%3}, [%4];"
                 : "=r"(r[0]), "=r"(r[1]), "=r"(r[2]), "=r"(r[3]) : "r"(addr));
}

// ===========================================================================
// NT GEMM on bf16 hi/lo planes (3-term emulation), 256 threads. [R10 core]
//   C[128x64] tile, 8 warps 4(M)x2(N), warp tile 32x32, 3 CTAs/SM.
// ===========================================================================
#define KB        32
#define NKB       16
#define STAGE     24576
#define GEMM_SMEM (3 * STAGE)   // 73728

template <int EPI>   // 0: fp32 C ; 1: bf16 hi/lo planes
__device__ __forceinline__ void gemm_nt_bf16(
    const __nv_bfloat16* __restrict__ Ah, const __nv_bfloat16* __restrict__ Al, int lda,
    const __nv_bfloat16* __restrict__ Bh, const __nv_bfloat16* __restrict__ Bl, int ldb,
    float* __restrict__ C, __nv_bfloat16* __restrict__ Ch,
    __nv_bfloat16* __restrict__ Cl, int ldc, int by, int bx)
{
    extern __shared__ __align__(128) char smc[];
    const uint32_t sa = smem_u32(smc);

    const int tid = threadIdx.x;
    const int wid = tid >> 5;
    const int lid = tid & 31;
    const int wr  = wid >> 1;          // 0..3 (M)
    const int wc  = wid & 1;           // 0..1 (N)
    const int g   = lid >> 2;
    const int tg  = lid & 3;

    const __nv_bfloat16* Abh = Ah + (size_t)(by * 128) * lda;
    const __nv_bfloat16* Abl = Al + (size_t)(by * 128) * lda;
    const __nv_bfloat16* Bbh = Bh + (size_t)(bx * 64) * ldb;
    const __nv_bfloat16* Bbl = Bl + (size_t)(bx * 64) * ldb;

    auto load_stage = [&](int buf, int kb) {
        const uint32_t dbase = sa + buf * STAGE;
        const int kc = kb * KB;
#pragma unroll
        for (int i = 0; i < 4; ++i) {               // A: 1024 chunks
            const int t = tid + (i << 8);
            const int row = t >> 3, c = t & 7;
            const __nv_bfloat16* src =
                ((c & 4) ? Abl : Abh) + (size_t)row * lda + kc + (c & 3) * 8;
            cp16(dbase + row * 128 + ((c ^ (row & 7)) << 4), src);
        }
        {
            const int t = tid + 1024;
            const int row = (t >> 3) & 63, c = t & 7;
            const __nv_bfloat16* src =
                ((c & 4) ? Bbl : Bbh) + (size_t)row * ldb + kc + (c & 3) * 8;
            cp16(dbase + 16384 + row * 128 + ((c ^ (row & 7)) << 4), src);
        }
        {
            const int t = tid + 1280;
            const int row = (t >> 3) & 63, c = t & 7;
            const __nv_bfloat16* src =
                ((c & 4) ? Bbl : Bbh) + (size_t)row * ldb + kc + (c & 3) * 8;
            cp16(dbase + 16384 + row * 128 + ((c ^ (row & 7)) << 4), src);
        }
    };

    float acc[2][4][4];
#pragma unroll
    for (int mt = 0; mt < 2; ++mt)
#pragma unroll
        for (int nt = 0; nt < 4; ++nt)
#pragma unroll
            for (int i = 0; i < 4; ++i) acc[mt][nt][i] = 0.0f;

    const uint32_t sx = (uint32_t)(lid & 7) << 4;
    const uint32_t hb = (uint32_t)(lid >> 4) << 4;
    uint32_t ra[2], rb[2];
#pragma unroll
    for (int mt = 0; mt < 2; ++mt)
        ra[mt] = (uint32_t)(wr * 32 + mt * 16 + (lid & 15)) * 128;
#pragma unroll
    for (int n2 = 0; n2 < 2; ++n2)
        rb[n2] = 16384u + (uint32_t)(wc * 32 + n2 * 16 + (lid & 15)) * 128;

    load_stage(0, 0); CP_COMMIT();
    load_stage(1, 1); CP_COMMIT();

#pragma unroll 1
    for (int kb = 0; kb < NKB; ++kb) {
        CP_WAIT1();
        __syncthreads();
        if (kb + 2 < NKB) load_stage((kb + 2) % 3, kb + 2);
        CP_COMMIT();

        const uint32_t sbase = sa + (kb % 3) * STAGE;

#pragma unroll
        for (int ks = 0; ks < 2; ++ks) {
            const uint32_t cvh = (uint32_t)(ks << 5) + hb;
            const uint32_t cvl = cvh + 64;

            uint32_t ah[2][4], al[2][4], bb[4][2];
#pragma unroll
            for (int mt = 0; mt < 2; ++mt) {
                ldsm4(ah[mt], sbase + ra[mt] + (cvh ^ sx));
                ldsm4(al[mt], sbase + ra[mt] + (cvl ^ sx));
            }
#pragma unroll
            for (int n2 = 0; n2 < 2; ++n2) {
                uint32_t r[4];
                ldsm4(r, sbase + rb[n2] + (cvh ^ sx));
                bb[n2 * 2][0] = r[0]; bb[n2 * 2][1] = r[2];
                bb[n2 * 2 + 1][0] = r[1]; bb[n2 * 2 + 1][1] = r[3];
            }
#pragma unroll
            for (int mt = 0; mt < 2; ++mt)
#pragma unroll
                for (int nt = 0; nt < 4; ++nt) mma16(acc[mt][nt], ah[mt], bb[nt]);
#pragma unroll
            for (int mt = 0; mt < 2; ++mt)
#pragma unroll
                for (int nt = 0; nt < 4; ++nt) mma16(acc[mt][nt], al[mt], bb[nt]);
#pragma unroll
            for (int n2 = 0; n2 < 2; ++n2) {
                uint32_t r[4];
                ldsm4(r, sbase + rb[n2] + (cvl ^ sx));
                bb[n2 * 2][0] = r[0]; bb[n2 * 2][1] = r[2];
                bb[n2 * 2 + 1][0] = r[1]; bb[n2 * 2 + 1][1] = r[3];
            }
#pragma unroll
            for (int mt = 0; mt < 2; ++mt)
#pragma unroll
                for (int nt = 0; nt < 4; ++nt) mma16(acc[mt][nt], ah[mt], bb[nt]);
        }
    }

    const int rbase = by * 128 + wr * 32 + g;
    const int cbase = bx * 64 + wc * 32 + tg * 2;
#pragma unroll
    for (int mt = 0; mt < 2; ++mt) {
#pragma unroll
        for (int nt = 0; nt < 4; ++nt) {
            const int r = rbase + mt * 16;
            const int c = cbase + nt * 8;
            if (EPI == 0) {
                *reinterpret_cast<float2*>(&C[(size_t)r * ldc + c]) =
                    make_float2(acc[mt][nt][0], acc[mt][nt][1]);
                *reinterpret_cast<float2*>(&C[(size_t)(r + 8) * ldc + c]) =
                    make_float2(acc[mt][nt][2], acc[mt][nt][3]);
            } else {
                uint32_t h, l;
                pack2(acc[mt][nt][0], acc[mt][nt][1], h, l);
                *reinterpret_cast<uint32_t*>(Ch + (size_t)r * ldc + c) = h;
                *reinterpret_cast<uint32_t*>(Cl + (size_t)r * ldc + c) = l;
                pack2(acc[mt][nt][2], acc[mt][nt][3], h, l);
                *reinterpret_cast<uint32_t*>(Ch + (size_t)(r + 8) * ldc + c) = h;
                *reinterpret_cast<uint32_t*>(Cl + (size_t)(r + 8) * ldc + c) = l;
            }
        }
    }
}

// ===========================================================================
// fp16 single-pass NT GEMM body (used by proj_v and pv). C tile 128x64.
// KB=64, stage 24KB (A 128 rows @0, B 64 rows @16K), 3 stages.
// EPI: 0 -> fp32 C (pv) ; 1 -> fused-transpose fp16 VT write (proj_v)
// ===========================================================================
template <int EPI>
__device__ __forceinline__ void gemm_nt_f16(
    const __half* __restrict__ Ab, const __half* __restrict__ Bb,
    float* __restrict__ C, int ldc, __half* __restrict__ VT,
    int rloc0, int cloc0)
{
    extern __shared__ __align__(128) char smc[];
    const uint32_t sa = smem_u32(smc);

    const int tid = threadIdx.x;
    const int wid = tid >> 5;
    const int lid = tid & 31;
    const int wr  = wid >> 1;
    const int wc  = wid & 1;
    const int g   = lid >> 2;
    const int tg  = lid & 3;

    auto load_stage = [&](int buf, int kb) {
        const uint32_t dbase = sa + buf * STAGE;
        const int kc = kb * 64;
#pragma unroll
        for (int i = 0; i < 4; ++i) {               // A: 1024 chunks
            const int t = tid + (i << 8);
            const int row = t >> 3, c = t & 7;
            cp16(dbase + row * 128 + ((c ^ (row & 7)) << 4),
                 Ab + (size_t)row * 512 + kc + c * 8);
        }
        {                                            // B: 512 chunks
            const int t = tid;
            const int row = t >> 3, c = t & 7;
            cp16(dbase + 16384 + row * 128 + ((c ^ (row & 7)) << 4),
                 Bb + (size_t)row * 512 + kc + c * 8);
        }
        {
            const int t = tid + 256;
            const int row = t >> 3, c = t & 7;
            cp16(dbase + 16384 + row * 128 + ((c ^ (row & 7)) << 4),
                 Bb + (size_t)row * 512 + kc + c * 8);
        }
    };

    float acc[2][4][4];
#pragma unroll
    for (int mt = 0; mt < 2; ++mt)
#pragma unroll
        for (int nt = 0; nt < 4; ++nt)
#pragma unroll
            for (int i = 0; i < 4; ++i) acc[mt][nt][i] = 0.0f;

    const uint32_t sx = (uint32_t)(lid & 7) << 4;
    const uint32_t hb = (uint32_t)(lid >> 4) << 4;
    uint32_t ra[2], rb[2];
#pragma unroll
    for (int mt = 0; mt < 2; ++mt)
        ra[mt] = (uint32_t)(wr * 32 + mt * 16 + (lid & 15)) * 128;
#pragma unroll
    for (int n2 = 0; n2 < 2; ++n2)
        rb[n2] = 16384u + (uint32_t)(wc * 32 + n2 * 16 + (lid & 15)) * 128;

    load_stage(0, 0); CP_COMMIT();
    load_stage(1, 1); CP_COMMIT();

#pragma unroll 1
    for (int kb = 0; kb < 8; ++kb) {
        CP_WAIT1();
        __syncthreads();
        if (kb + 2 < 8) load_stage((kb + 2) % 3, kb + 2);
        CP_COMMIT();

        const uint32_t sbase = sa + (kb % 3) * STAGE;

#pragma unroll
        for (int ks = 0; ks < 4; ++ks) {
            const uint32_t cv = (uint32_t)(ks << 5) + hb;

            uint32_t ah[2][4], bb[4][2];
#pragma unroll
            for (int mt = 0; mt < 2; ++mt)
                ldsm4(ah[mt], sbase + ra[mt] + (cv ^ sx));
#pragma unroll
            for (int n2 = 0; n2 < 2; ++n2) {
                uint32_t r[4];
                ldsm4(r, sbase + rb[n2] + (cv ^ sx));
                bb[n2 * 2][0] = r[0]; bb[n2 * 2][1] = r[2];
                bb[n2 * 2 + 1][0] = r[1]; bb[n2 * 2 + 1][1] = r[3];
            }
#pragma unroll
            for (int mt = 0; mt < 2; ++mt)
#pragma unroll
                for (int nt = 0; nt < 4; ++nt) mma16f(acc[mt][nt], ah[mt], bb[nt]);
        }
    }

    const int rbase = rloc0 + wr * 32 + g;
    const int cbase = cloc0 + wc * 32 + tg * 2;
#pragma unroll
    for (int mt = 0; mt < 2; ++mt) {
#pragma unroll
        for (int nt = 0; nt < 4; ++nt) {
            const int r = rbase + mt * 16;
            const int c = cbase + nt * 8;
            if (EPI == 0) {
                *reinterpret_cast<float2*>(&C[(size_t)r * ldc + c]) =
                    make_float2(acc[mt][nt][0], acc[mt][nt][1]);
                *reinterpret_cast<float2*>(&C[(size_t)(r + 8) * ldc + c]) =
                    make_float2(acc[mt][nt][2], acc[mt][nt][3]);
            } else {
                __half2 v0 = __floats2half2_rn(acc[mt][nt][0], acc[mt][nt][1]);
                __half2 v1 = __floats2half2_rn(acc[mt][nt][2], acc[mt][nt][3]);
                *reinterpret_cast<__half2*>(VT + (size_t)r * 512 + c)       = v0;
                *reinterpret_cast<__half2*>(VT + (size_t)(r + 8) * 512 + c) = v1;
            }
        }
    }
}

// ===========================================================================
// Q,K projections (bf16 3-term)
// ===========================================================================
__global__ void __launch_bounds__(256, 3)
proj_mm()
{
    const int z = blockIdx.z;                 // 0:Q 1:K
    const __nv_bfloat16* Bh = g_WTh + (size_t)z * 4096 * 512;
    const __nv_bfloat16* Bl = g_WTl + (size_t)z * 4096 * 512;
    if (z == 0)
        gemm_nt_bf16<1>(g_xh, g_xl, 512, Bh, Bl, 512, nullptr, g_Qh, g_Ql, 4096,
                        blockIdx.y, blockIdx.x);
    else
        gemm_nt_bf16<1>(g_xh, g_xl, 512, Bh, Bl, 512, nullptr, g_Kh, g_Kl, 4096,
                        blockIdx.y, blockIdx.x);
}

// ===========================================================================
// Merged launch: z<128 -> qk tile; z>=128 -> proj_v tile (independent work,
// overlapping wave tails).
// ===========================================================================
__global__ void __launch_bounds__(256, 3)
qk_projv()
{
    const int z = blockIdx.z;
    if (z < 128) {
        // ---- QK^T: scores[z] tile (by 128 q-rows, bx 64 k-rows) ----
        const int h = z >> 4, b = z & 15;
        const size_t off = (size_t)b * 512 * 4096 + h * 512;
        gemm_nt_bf16<0>(g_Qh + off, g_Ql + off, 4096,
                        g_Kh + off, g_Kl + off, 4096,
                        g_P + (size_t)z * 512 * 512, nullptr, nullptr, 512,
                        blockIdx.y, blockIdx.x);
    } else {
        // ---- V projection with fused transpose (4096 tiles, flat remap) ----
        const int t  = (z - 128) * 32 + blockIdx.y * 8 + blockIdx.x;
        const int vx = t & 127;               // token-tile (64 tokens)
        const int vy = t >> 7;                // d-tile (128 dcols)
        const __half* Ab = g_WV16 + (size_t)vy * 128 * 512;
        const __half* Bb = g_x16  + (size_t)vx * 64 * 512;
        const int hH = vy >> 2, bB = vx >> 3;
        __half* VT = g_VT + (size_t)(hH * 16 + bB) * 262144;
        gemm_nt_f16<1>(Ab, Bb, nullptr, 0, VT,
                       (vy & 3) * 128, (vx & 7) * 64);
    }
}

// ===========================================================================
// PV GEMM: single fp16 P x single fp16 V, 1 MMA pass. C[128x64] fp32.
// ===========================================================================
__global__ void __launch_bounds__(256, 3)
pv_mm(float* __restrict__ out)
{
    const int z = blockIdx.z;
    const int h = z >> 4, b = z & 15;
    const size_t zo = (size_t)z * 262144;
    const __half* Ab = g_Pf + zo + (size_t)(blockIdx.y * 128) * 512;
    const __half* Bb = g_VT + zo + (size_t)(blockIdx.x * 64) * 512;
    float* C = out + (size_t)b * 512 * 4096 + h * 512;
    gemm_nt_f16<0>(Ab, Bb, C, 4096, nullptr,
                   blockIdx.y * 128, blockIdx.x * 64);
}

// ===========================================================================
// Prep kernels
// ===========================================================================
__global__ void split_x(const float* __restrict__ x)
{
    const size_t i = ((size_t)blockIdx.x * 256 + threadIdx.x) * 4;
    const float4 v = *reinterpret_cast<const float4*>(x + i);
    uint32_t h0, l0, h1, l1;
    pack2(v.x, v.y, h0, l0);
    pack2(v.z, v.w, h1, l1);
    *reinterpret_cast<uint2*>(g_xh + i) = make_uint2(h0, h1);
    *reinterpret_cast<uint2*>(g_xl + i) = make_uint2(l0, l1);
    __half2 a = __floats2half2_rn(v.x, v.y);
    __half2 b = __floats2half2_rn(v.z, v.w);
    *reinterpret_cast<__half2*>(g_x16 + i)     = a;
    *reinterpret_cast<__half2*>(g_x16 + i + 2) = b;
}

// z=0: wq (bf16 planes), z=1: wk (bf16 planes), z=2: wv (fp16 single)
__global__ void wt_all(const float* __restrict__ wq,
                       const float* __restrict__ wk,
                       const float* __restrict__ wv)
{
    __shared__ float t[32][33];
    const int z = blockIdx.z;
    const float* W = (z == 0) ? wq : (z == 1) ? wk : wv;   // [512, 4096]
    const int n0 = blockIdx.x * 32, k0 = blockIdx.y * 32;
    const int tx = threadIdx.x, ty = threadIdx.y;
#pragma unroll
    for (int i = 0; i < 4; ++i)
        t[ty + i * 8][tx] = W[(size_t)(k0 + ty + i * 8) * 4096 + n0 + tx];
    __syncthreads();
    if (z < 2) {
        __nv_bfloat16* WTh = g_WTh + (size_t)z * 4096 * 512;
        __nv_bfloat16* WTl = g_WTl + (size_t)z * 4096 * 512;
#pragma unroll
        for (int i = 0; i < 4; ++i) {
            const float v = t[tx][ty + i * 8];
            const __nv_bfloat16 hbf = __float2bfloat16_rn(v);
            const float lo = v - __bfloat162float(hbf);
            const size_t idx = (size_t)(n0 + ty + i * 8) * 512 + k0 + tx;
            WTh[idx] = hbf;
            WTl[idx] = __float2bfloat16_rn(lo);
        }
    } else {
#pragma unroll
        for (int i = 0; i < 4; ++i) {
            const float v = t[tx][ty + i * 8];
            g_WV16[(size_t)(n0 + ty + i * 8) * 512 + k0 + tx] = __float2half_rn(v);
        }
    }
}

// ===========================================================================
// Softmax over rows of g_P (512 wide), writes single fp16 plane g_Pf.
// ===========================================================================
__global__ void softmax_kernel()
{
    const size_t row = blockIdx.x;
    const float* p = g_P + row * 512;
    const int t = threadIdx.x;

    float2 v = reinterpret_cast<const float2*>(p)[t];
    __shared__ float red[8];

    float m = fmaxf(v.x, v.y);
#pragma unroll
    for (int o = 16; o > 0; o >>= 1) m = fmaxf(m, __shfl_xor_sync(0xFFFFFFFFu, m, o));
    if ((t & 31) == 0) red[t >> 5] = m;
    __syncthreads();
    m = red[0];
#pragma unroll
    for (int i = 1; i < 8; i++) m = fmaxf(m, red[i]);
    __syncthreads();

    const float e0 = __expf(v.x - m);
    const float e1 = __expf(v.y - m);

    float s = e0 + e1;
#pragma unroll
    for (int o = 16; o > 0; o >>= 1) s += __shfl_xor_sync(0xFFFFFFFFu, s, o);
    if ((t & 31) == 0) red[t >> 5] = s;
    __syncthreads();
    s = red[0];
#pragma unroll
    for (int i = 1; i < 8; i++) s += red[i];

    const float inv = 1.0f / s;
    reinterpret_cast<__half2*>(g_Pf + row * 512)[t] =
        __floats2half2_rn(e0 * inv, e1 * inv);
}

// ===========================================================================
// Launch
// ===========================================================================
extern "C" void kernel_launch(void* const* d_in, const int* in_sizes, int n_in,
                              void* d_out, int out_size)
{
    const float* x  = (const float*)d_in[0];
    const float* wq = (const float*)d_in[1];
    const float* wk = (const float*)d_in[2];
    const float* wv = (const float*)d_in[3];
    float* out = (float*)d_out;

    cudaFuncSetAttribute(proj_mm,  cudaFuncAttributeMaxDynamicSharedMemorySize, GEMM_SMEM);
    cudaFuncSetAttribute(qk_projv, cudaFuncAttributeMaxDynamicSharedMemorySize, GEMM_SMEM);
    cudaFuncSetAttribute(pv_mm,    cudaFuncAttributeMaxDynamicSharedMemorySize, GEMM_SMEM);

    split_x<<<4096, 256>>>(x);                                   // 1
    wt_all<<<dim3(128, 16, 3), dim3(32, 8)>>>(wq, wk, wv);       // 2
    proj_mm<<<dim3(64, 64, 2), 256, GEMM_SMEM>>>();              // 3
    qk_projv<<<dim3(8, 4, 256), 256, GEMM_SMEM>>>();             // 4 <- profiled
    softmax_kernel<<<65536, 256>>>();                            // 5
    pv_mm<<<dim3(8, 4, 128), 256, GEMM_SMEM>>>(out);             // 6
}